// round 6
// baseline (speedup 1.0000x reference)
#include <cuda_runtime.h>
#include <math.h>
#include <stdint.h>

#define NPB    16384
#define NTOT   65536
#define C_     256
#define INNER  512
#define QKVN   1536
#define HEADS  8
#define DH     64
#define NBF    256
#define BH     32
#define EPS_   1e-4f
#define DN_    0.3535533905932738f
#define RATIO_ 0.0625f
#define KSPLITS 32
#define NEG_INF_ -3.0e38f

// ---------------- scratch ----------------
__device__ float g_qkv [(size_t)NTOT * QKVN];
__device__ float g_Wqkv[(size_t)C_ * QKVN];
__device__ float g_projT[DH * NBF];
__device__ float g_kmax[BH];
__device__ float g_pctx [(size_t)BH * KSPLITS * NBF * DH];
__device__ float g_pksum[(size_t)BH * KSPLITS * 4 * NBF];
__device__ float g_pvsum[(size_t)BH * KSPLITS * DH];
__device__ float g_ctx  [(size_t)BH * NBF * DH];
__device__ float g_ksum [(size_t)BH * NBF];
__device__ float g_attn[(size_t)NTOT * INNER];
__device__ float g_WoWp[(size_t)INNER * C_];
__device__ float g_bvec[C_];
__device__ float g_wpcol[C_];

static __device__ __forceinline__ void atomicMaxFloat(float* addr, float val) {
    int* ia = (int*)addr;
    int old = *ia;
    while (__int_as_float(old) < val) {
        int assumed = old;
        old = atomicCAS(ia, assumed, __float_as_int(val));
        if (old == assumed) break;
    }
}

// ---------------- prep ----------------
__global__ __launch_bounds__(256) void prep_kernel(
    const float* __restrict__ Wo, const float* __restrict__ bo,
    const float* __restrict__ Wp, const float* __restrict__ bp)
{
    int i = blockIdx.x, j = threadIdx.x;
    if (i < INNER) {
        __shared__ float wrow[C_];
        wrow[j] = Wo[i * C_ + j];
        __syncthreads();
        float s = 0.f;
        #pragma unroll 8
        for (int c = 0; c < C_; c++) s += wrow[c] * Wp[c * C_ + j];
        g_WoWp[i * C_ + j] = s;
    } else {
        float s = 0.f, w = 0.f;
        for (int c = 0; c < C_; c++) { float wp = Wp[c * C_ + j]; s += bo[c] * wp; w += wp; }
        g_bvec[j]  = s + bp[j];
        g_wpcol[j] = w;
        if (j < BH) g_kmax[j] = NEG_INF_;
    }
}

__global__ void projprep_kernel(const float* __restrict__ proj) {
    int d = blockIdx.x, f = threadIdx.x;
    g_projT[d * NBF + f] = proj[f * DH + d] * DN_;
}

__global__ __launch_bounds__(512) void pack_wqkv_kernel(
    const float* __restrict__ Wq, const float* __restrict__ Wk, const float* __restrict__ Wv)
{
    int i = blockIdx.x;
    int j = threadIdx.x;
    g_Wqkv[(size_t)i * QKVN + j]        = Wq[(size_t)i * INNER + j];
    g_Wqkv[(size_t)i * QKVN + 512 + j]  = Wk[(size_t)i * INNER + j];
    g_Wqkv[(size_t)i * QKVN + 1024 + j] = Wv[(size_t)i * INNER + j];
}

// ==================== common MMA helpers ====================
static __device__ __forceinline__ void cp_async16(float* s, const float* g) {
    unsigned saddr = (unsigned)__cvta_generic_to_shared(s);
    asm volatile("cp.async.cg.shared.global [%0], [%1], 16;\n" :: "r"(saddr), "l"(g));
}
#define CP_COMMIT() asm volatile("cp.async.commit_group;\n")
#define CP_WAIT0()  asm volatile("cp.async.wait_group 0;\n")

static __device__ __forceinline__ uint32_t f2tf(float x) {
    uint32_t r; asm("cvt.rna.tf32.f32 %0, %1;" : "=r"(r) : "f"(x)); return r;
}
static __device__ __forceinline__ void mma_tf32(float* c, const uint32_t* a, const uint32_t* b) {
    asm volatile("mma.sync.aligned.m16n8k8.row.col.f32.tf32.tf32.f32 "
        "{%0,%1,%2,%3},{%4,%5,%6,%7},{%8,%9},{%0,%1,%2,%3};"
        : "+f"(c[0]), "+f"(c[1]), "+f"(c[2]), "+f"(c[3])
        : "r"(a[0]), "r"(a[1]), "r"(a[2]), "r"(a[3]), "r"(b[0]), "r"(b[1]));
}

#define PJ_ST 264
#define AT_ST 68
#define VT_ST 72
#define KP_ST 76
#define QP_ST 260
#define CX_ST 72

// 512-thread loaders
static __device__ __forceinline__ void load_projT_512(float* ps, int t) {
    #pragma unroll
    for (int i = 0; i < 8; i++) {
        int idx = t + i * 512;
        int r = idx >> 6, c4 = (idx & 63) * 4;
        cp_async16(&ps[r * PJ_ST + c4], g_projT + r * 256 + c4);
    }
}
template<int ST>
static __device__ __forceinline__ void load_tile64_512(float* s, int b, int h, int n0, int off, int t) {
    #pragma unroll
    for (int i = 0; i < 2; i++) {
        int idx = t + i * 512;
        int r = idx >> 4, c4 = (idx & 15) * 4;
        cp_async16(&s[r * ST + c4],
            g_qkv + (size_t)(b * NPB + n0 + r) * QKVN + off + h * DH + c4);
    }
}

// dd[n][f] = tile @ projT, 16-warp version: each warp 16 rows x 64 cols
static __device__ __forceinline__ void mma_dd16(
    const float* __restrict__ As, const float* __restrict__ Ps,
    float acc[8][4], int warpM, int warpN, int g, int tg)
{
    #pragma unroll
    for (int kk = 0; kk < 8; kk++) {
        uint32_t af[4], bf[8][2];
        const float* a = As + (warpM * 16 + g) * AT_ST + kk * 8 + tg;
        af[0] = f2tf(a[0]);
        af[1] = f2tf(a[8 * AT_ST]);
        af[2] = f2tf(a[4]);
        af[3] = f2tf(a[8 * AT_ST + 4]);
        #pragma unroll
        for (int nt = 0; nt < 8; nt++) {
            const float* bp_ = Ps + (kk * 8 + tg) * PJ_ST + warpN * 64 + nt * 8 + g;
            bf[nt][0] = f2tf(bp_[0]);
            bf[nt][1] = f2tf(bp_[4 * PJ_ST]);
        }
        #pragma unroll
        for (int nt = 0; nt < 8; nt++)
            mma_tf32(acc[nt], af, bf[nt]);
    }
}

// ==================== K2: key features -> partial (unscaled) ctx/ksum + max + vsum ====
#define K2_SMEM ((64*PJ_ST + 2*64*AT_ST + 2*64*VT_ST + 256*KP_ST + 64 + 512) * 4)
__global__ __launch_bounds__(512, 1) void kctx_kernel2()
{
    extern __shared__ float sm[];
    float* Ps    = sm;
    float* Ks    = Ps + 64 * PJ_ST;
    float* Vs    = Ks + 2 * 64 * AT_ST;
    float* KPs   = Vs + 2 * 64 * VT_ST;
    float* sdiag = KPs + 256 * KP_ST;
    float* red   = sdiag + 64;
    int t = threadIdx.x;
    int bh = blockIdx.y, b = bh >> 3, h = bh & 7;
    int sp = blockIdx.x;
    int warp = t >> 5, lane = t & 31, g = lane >> 2, tg = lane & 3;
    int warpM = warp >> 2, warpN = warp & 3;     // dd: 4x4 warps, 16x64 each
    int warpM2 = warp >> 1, warpN2 = warp & 1;   // ctx: 8x2 warps, 32f x 32d each

    load_projT_512(Ps, t);
    float acc2[2][4][4];
    #pragma unroll
    for (int a = 0; a < 2; a++)
        #pragma unroll
        for (int bq = 0; bq < 4; bq++)
            #pragma unroll
            for (int r = 0; r < 4; r++) acc2[a][bq][r] = 0.f;
    float ksacc[8][2];
    #pragma unroll
    for (int nt = 0; nt < 8; nt++) { ksacc[nt][0] = 0.f; ksacc[nt][1] = 0.f; }
    float tmax = NEG_INF_;
    float vsum_acc = 0.f;

    load_tile64_512<AT_ST>(Ks, b, h, sp * 512, 512, t);
    load_tile64_512<VT_ST>(Vs, b, h, sp * 512, 1024, t);
    CP_COMMIT();

    for (int c = 0; c < 8; c++) {
        CP_WAIT0();
        __syncthreads();
        float* Kb = Ks + (c & 1) * 64 * AT_ST;
        float* Vb = Vs + (c & 1) * 64 * VT_ST;
        if (c + 1 < 8) {
            int n1 = sp * 512 + (c + 1) * 64;
            load_tile64_512<AT_ST>(Ks + ((c + 1) & 1) * 64 * AT_ST, b, h, n1, 512, t);
            load_tile64_512<VT_ST>(Vs + ((c + 1) & 1) * 64 * VT_ST, b, h, n1, 1024, t);
            CP_COMMIT();
        }
        if (t < 64) {
            float s = 0.f, vs = 0.f;
            #pragma unroll 8
            for (int r = 0; r < 64; r++) {
                float kv = Kb[t * AT_ST + r];
                s += kv * kv;
                vs += Vb[r * VT_ST + t];
            }
            sdiag[t] = 0.5f * s * (DN_ * DN_);
            vsum_acc += vs;
        }

        float acc[8][4];
        #pragma unroll
        for (int nt = 0; nt < 8; nt++)
            #pragma unroll
            for (int r = 0; r < 4; r++) acc[nt][r] = 0.f;
        mma_dd16(Kb, Ps, acc, warpM, warpN, g, tg);
        __syncthreads();    // sdiag visible; mma reads of Kb done

        int n_a = warpM * 16 + g;
        int n_b = n_a + 8;
        float da = sdiag[n_a], db = sdiag[n_b];
        #pragma unroll
        for (int nt = 0; nt < 8; nt++) {
            int f0 = warpN * 64 + nt * 8 + tg * 2;
            float d0 = acc[nt][0], d1 = acc[nt][1];
            float d2 = acc[nt][2], d3 = acc[nt][3];
            tmax = fmaxf(tmax, fmaxf(fmaxf(d0, d1), fmaxf(d2, d3)));
            float k0 = __expf(d0 - da);
            float k1 = __expf(d1 - da);
            float k2 = __expf(d2 - db);
            float k3 = __expf(d3 - db);
            KPs[f0 * KP_ST + n_a]       = k0;
            KPs[(f0 + 1) * KP_ST + n_a] = k1;
            KPs[f0 * KP_ST + n_b]       = k2;
            KPs[(f0 + 1) * KP_ST + n_b] = k3;
            float s0 = k0 + k2, s1 = k1 + k3;
            #pragma unroll
            for (int o = 4; o <= 16; o <<= 1) {
                s0 += __shfl_xor_sync(0xffffffffu, s0, o);
                s1 += __shfl_xor_sync(0xffffffffu, s1, o);
            }
            ksacc[nt][0] += s0; ksacc[nt][1] += s1;
        }
        __syncthreads();    // KPs visible

        // ctx += kp^T @ v : raw-bit tf32 (post-exp linear path)
        #pragma unroll
        for (int kk = 0; kk < 8; kk++) {
            uint32_t af[2][4], bf[4][2];
            #pragma unroll
            for (int mt2 = 0; mt2 < 2; mt2++) {
                const float* a = KPs + (warpM2 * 32 + mt2 * 16 + g) * KP_ST + kk * 8 + tg;
                af[mt2][0] = __float_as_uint(a[0]);
                af[mt2][1] = __float_as_uint(a[8 * KP_ST]);
                af[mt2][2] = __float_as_uint(a[4]);
                af[mt2][3] = __float_as_uint(a[8 * KP_ST + 4]);
            }
            #pragma unroll
            for (int nt2 = 0; nt2 < 4; nt2++) {
                const float* bp_ = Vb + (kk * 8 + tg) * VT_ST + warpN2 * 32 + nt2 * 8 + g;
                bf[nt2][0] = __float_as_uint(bp_[0]);
                bf[nt2][1] = __float_as_uint(bp_[4 * VT_ST]);
            }
            #pragma unroll
            for (int mt2 = 0; mt2 < 2; mt2++)
                #pragma unroll
                for (int nt2 = 0; nt2 < 4; nt2++)
                    mma_tf32(acc2[mt2][nt2], af[mt2], bf[nt2]);
        }
    }

    red[t] = tmax; __syncthreads();
    for (int s = 256; s > 0; s >>= 1) {
        if (t < s) red[t] = fmaxf(red[t], red[t + s]);
        __syncthreads();
    }
    if (t == 0) atomicMaxFloat(&g_kmax[bh], red[0]);

    float* outp = g_pctx + ((size_t)bh * KSPLITS + sp) * NBF * DH;
    #pragma unroll
    for (int mt2 = 0; mt2 < 2; mt2++) {
        int f = warpM2 * 32 + mt2 * 16 + g;
        #pragma unroll
        for (int nt2 = 0; nt2 < 4; nt2++) {
            int d = warpN2 * 32 + nt2 * 8 + tg * 2;
            *(float2*)(outp + (size_t)f * DH + d)       = make_float2(acc2[mt2][nt2][0], acc2[mt2][nt2][1]);
            *(float2*)(outp + (size_t)(f + 8) * DH + d) = make_float2(acc2[mt2][nt2][2], acc2[mt2][nt2][3]);
        }
    }
    if (g == 0) {
        float* kout = g_pksum + (((size_t)bh * KSPLITS + sp) * 4 + warpM) * NBF;
        #pragma unroll
        for (int nt = 0; nt < 8; nt++) {
            int f0 = warpN * 64 + nt * 8 + tg * 2;
            kout[f0]     = ksacc[nt][0];
            kout[f0 + 1] = ksacc[nt][1];
        }
    }
    if (t < 64) g_pvsum[((size_t)bh * KSPLITS + sp) * DH + t] = vsum_acc;
}

// ---------------- deterministic reduction with rescale + EPS terms ----------------
__global__ __launch_bounds__(256) void reduce2_kernel()
{
    int idx = blockIdx.x * 256 + threadIdx.x;
    int bh = idx >> 14;
    int rem = idx & 16383;
    int d = rem & 63;
    float m = g_kmax[bh];
    float sc = RATIO_ * __expf(-m);
    float s = 0.f;
    const float* base = g_pctx + (size_t)bh * KSPLITS * NBF * DH + rem;
    #pragma unroll 8
    for (int sp = 0; sp < KSPLITS; sp++) s += base[(size_t)sp * NBF * DH];
    float vs = 0.f;
    const float* vb = g_pvsum + (size_t)bh * KSPLITS * DH + d;
    #pragma unroll 8
    for (int sp = 0; sp < KSPLITS; sp++) vs += vb[sp * DH];
    g_ctx[idx] = sc * s + (RATIO_ * EPS_) * vs;
    if (idx < BH * NBF) {
        int bh2 = idx >> 8, f = idx & 255;
        float m2 = g_kmax[bh2];
        float s2 = 0.f;
        const float* kb = g_pksum + (size_t)bh2 * KSPLITS * 4 * NBF + f;
        for (int j = 0; j < KSPLITS * 4; j++) s2 += kb[j * NBF];
        g_ksum[idx] = RATIO_ * __expf(-m2) * s2 + (RATIO_ * EPS_) * (float)NPB;
    }
}

// ==================== Q: fused query features + attention (512 threads) ====
#define Q_SMEM ((64*PJ_ST + 256*CX_ST + 64*AT_ST + 64*QP_ST + 256 + 64 + 256 + 64) * 4)
__global__ __launch_bounds__(512, 1) void qattn_kernel()
{
    extern __shared__ float sm[];
    float* Ps   = sm;
    float* Cs   = Ps + 64 * PJ_ST;
    float* Qs   = Cs + 256 * CX_ST;
    float* QPs  = Qs + 64 * AT_ST;
    float* sks  = QPs + 64 * QP_ST;
    float* sdq  = sks + 256;
    float* rowr = sdq + 64;
    float* srow = rowr + 256;
    int t = threadIdx.x;
    int bh = blockIdx.y, b = bh >> 3, h = bh & 7;
    int warp = t >> 5, lane = t & 31, g = lane >> 2, tg = lane & 3;
    int warpM = warp >> 2, warpN = warp & 3;     // dd: 4x4 warps, 16x64; attn: 16n x 16d

    load_projT_512(Ps, t);
    #pragma unroll
    for (int i = 0; i < 8; i++) {
        int idx = t + i * 512;
        int r = idx >> 4, c4 = (idx & 15) * 4;
        cp_async16(&Cs[r * CX_ST + c4], g_ctx + (size_t)bh * NBF * DH + r * DH + c4);
    }
    if (t < 256) sks[t] = g_ksum[bh * NBF + t];

    for (int c = 0; c < 2; c++) {
        int n0 = blockIdx.x * 128 + c * 64;
        load_tile64_512<AT_ST>(Qs, b, h, n0, 0, t);
        CP_COMMIT(); CP_WAIT0();
        __syncthreads();
        if (t < 64) {
            float s = 0.f;
            #pragma unroll
            for (int d = 0; d < 64; d++) { float qv = Qs[t * AT_ST + d]; s += qv * qv; }
            sdq[t] = 0.5f * s * (DN_ * DN_);
        }

        float acc[8][4];
        #pragma unroll
        for (int nt = 0; nt < 8; nt++)
            #pragma unroll
            for (int r = 0; r < 4; r++) acc[nt][r] = 0.f;
        mma_dd16(Qs, Ps, acc, warpM, warpN, g, tg);

        {
            float r0m = NEG_INF_, r1m = NEG_INF_;
            #pragma unroll
            for (int nt = 0; nt < 8; nt++) {
                r0m = fmaxf(r0m, fmaxf(acc[nt][0], acc[nt][1]));
                r1m = fmaxf(r1m, fmaxf(acc[nt][2], acc[nt][3]));
            }
            r0m = fmaxf(r0m, __shfl_xor_sync(0xffffffffu, r0m, 1));
            r0m = fmaxf(r0m, __shfl_xor_sync(0xffffffffu, r0m, 2));
            r1m = fmaxf(r1m, __shfl_xor_sync(0xffffffffu, r1m, 1));
            r1m = fmaxf(r1m, __shfl_xor_sync(0xffffffffu, r1m, 2));
            if (tg == 0) {
                int n_a = warpM * 16 + g;
                rowr[warpN * 64 + n_a]     = r0m;
                rowr[warpN * 64 + n_a + 8] = r1m;
            }
        }
        __syncthreads();    // rowr + sdq visible
        if (t < 64)
            srow[t] = fmaxf(fmaxf(rowr[t], rowr[64 + t]), fmaxf(rowr[128 + t], rowr[192 + t]));
        __syncthreads();

        {
            int n_a = warpM * 16 + g;
            int n_b = n_a + 8;
            float oa = sdq[n_a] + srow[n_a], ob = sdq[n_b] + srow[n_b];
            float d0 = 0.f, d1 = 0.f;
            #pragma unroll
            for (int nt = 0; nt < 8; nt++) {
                int f0 = warpN * 64 + nt * 8 + tg * 2;
                float q0 = RATIO_ * (__expf(acc[nt][0] - oa) + EPS_);
                float q1 = RATIO_ * (__expf(acc[nt][1] - oa) + EPS_);
                float q2 = RATIO_ * (__expf(acc[nt][2] - ob) + EPS_);
                float q3 = RATIO_ * (__expf(acc[nt][3] - ob) + EPS_);
                acc[nt][0] = q0; acc[nt][1] = q1;
                acc[nt][2] = q2; acc[nt][3] = q3;
                float ks0 = sks[f0], ks1 = sks[f0 + 1];
                d0 += q0 * ks0 + q1 * ks1;
                d1 += q2 * ks0 + q3 * ks1;
            }
            d0 += __shfl_xor_sync(0xffffffffu, d0, 1);
            d0 += __shfl_xor_sync(0xffffffffu, d0, 2);
            d1 += __shfl_xor_sync(0xffffffffu, d1, 1);
            d1 += __shfl_xor_sync(0xffffffffu, d1, 2);
            if (tg == 0) {
                rowr[warpN * 64 + n_a] = d0;
                rowr[warpN * 64 + n_b] = d1;
            }
        }
        __syncthreads();
        if (t < 64)
            srow[t] = 1.0f / (rowr[t] + rowr[64 + t] + rowr[128 + t] + rowr[192 + t]);
        __syncthreads();

        {
            int n_a = warpM * 16 + g;
            int n_b = n_a + 8;
            float ia = srow[n_a], ib = srow[n_b];
            #pragma unroll
            for (int nt = 0; nt < 8; nt++) {
                int f0 = warpN * 64 + nt * 8 + tg * 2;
                QPs[n_a * QP_ST + f0]     = acc[nt][0] * ia;
                QPs[n_a * QP_ST + f0 + 1] = acc[nt][1] * ia;
                QPs[n_b * QP_ST + f0]     = acc[nt][2] * ib;
                QPs[n_b * QP_ST + f0 + 1] = acc[nt][3] * ib;
            }
        }
        __syncthreads();

        // attn = qpt @ ctx : 16 warps, 16n x 16d each; raw-bit tf32
        float acc3[2][4];
        #pragma unroll
        for (int nt3 = 0; nt3 < 2; nt3++)
            #pragma unroll
            for (int r = 0; r < 4; r++) acc3[nt3][r] = 0.f;
        #pragma unroll 4
        for (int kk = 0; kk < 32; kk++) {
            uint32_t af[4], bf[2][2];
            const float* a = QPs + (warpM * 16 + g) * QP_ST + kk * 8 + tg;
            af[0] = __float_as_uint(a[0]);
            af[1] = __float_as_uint(a[8 * QP_ST]);
            af[2] = __float_as_uint(a[4]);
            af[3] = __float_as_uint(a[8 * QP_ST + 4]);
            #pragma unroll
            for (int nt3 = 0; nt3 < 2; nt3++) {
                const float* bp_ = Cs + (kk * 8 + tg) * CX_ST + warpN * 16 + nt3 * 8 + g;
                bf[nt3][0] = __float_as_uint(bp_[0]);
                bf[nt3][1] = __float_as_uint(bp_[4 * CX_ST]);
            }
            #pragma unroll
            for (int nt3 = 0; nt3 < 2; nt3++)
                mma_tf32(acc3[nt3], af, bf[nt3]);
        }
        float* ob2 = g_attn + (size_t)(b * NPB + n0) * INNER + h * DH;
        {
            int n = warpM * 16 + g;
            #pragma unroll
            for (int nt3 = 0; nt3 < 2; nt3++) {
                int d = warpN * 16 + nt3 * 8 + tg * 2;
                *(float2*)(ob2 + (size_t)n * INNER + d)       = make_float2(acc3[nt3][0], acc3[nt3][1]);
                *(float2*)(ob2 + (size_t)(n + 8) * INNER + d) = make_float2(acc3[nt3][2], acc3[nt3][3]);
            }
        }
        __syncthreads();
    }
}

// ==================== TF32 MMA GEMM (3-stage pipeline) ====================
#define BM 128
#define BN 128
#define BKT 32
#define AS_ST 36
#define BS_ST 136
#define GEMM_SMEM ((3*BM*AS_ST + 3*BKT*BS_ST) * 4)

template<int CVT, bool EPI>
__global__ __launch_bounds__(256, 2) void mma_gemm_kernel(
    const float* __restrict__ A, const float* __restrict__ B, float* __restrict__ C,
    int N, int K, const float* __restrict__ bt)
{
    extern __shared__ float smem[];
    float* As = smem;
    float* Bs = smem + 3 * BM * AS_ST;

    int tid = threadIdx.x;
    int lane = tid & 31, warp = tid >> 5;
    int wr = warp >> 2, wc = warp & 3;
    int g = lane >> 2, tg = lane & 3;

    float acc[4][4][4];
    #pragma unroll
    for (int mt = 0; mt < 4; mt++)
        #pragma unroll
        for (int nt = 0; nt < 4; nt++)
            #pragma unroll
            for (int r = 0; r < 4; r++) acc[mt][nt][r] = 0.f;

    const float* Abase = A + (size_t)blockIdx.y * BM * K;
    const float* Bbase = B + (size_t)blockIdx.x * BN;

    auto load_tile = [&](int kt, int buf) {
        const float* Ag = Abase + kt * BKT;
        #pragma unroll
        for (int i = 0; i < 4; i++) {
            int idx = tid + i * 256;
            int row = idx >> 3, c4 = (idx & 7) * 4;
            cp_async16(&As[buf * BM * AS_ST + row * AS_ST + c4], Ag + (size_t)row * K + c4);
        }
        const float* Bg = Bbase + (size_t)(kt * BKT) * N;
        #pragma unroll
        for (int i = 0; i < 4; i++) {
            int idx = tid + i * 256;
            int row = idx >> 5, c4 = (idx & 31) * 4;
            cp_async16(&Bs[buf * BKT * BS_ST + row * BS_ST + c4], Bg + (size_t)row * N + c4);
        }
        CP_COMMIT();
    };

    int KT = K / BKT;
    load_tile(0, 0);
    load_tile(1, 1);

    for (int kt = 0; kt < KT; kt++) {
        if (kt + 1 < KT) { asm volatile("cp.async.wait_group 1;\n"); }
        else             { asm volatile("cp.async.wait_group 0;\n"); }
        __syncthreads();
        if (kt + 2 < KT) load_tile(kt + 2, (kt + 2) % 3);

        const float* Ab = &As[(kt % 3) * BM * AS_ST];
        const float* Bb = &Bs[(kt % 3) * BKT * BS_ST];

        #pragma unroll
        for (int kk = 0; kk < 4; kk++) {
            uint32_t af[4][4], bf[4][2];
            #pragma unroll
            for (int mt = 0; mt < 4; mt++) {
                const float* base = Ab + (wr * 64 + mt * 16 + g) * AS_ST + kk * 8 + tg;
                float x0 = base[0];
                float x1 = base[8 * AS_ST];
                float x2 = base[4];
                float x3 = base[8 * AS_ST + 4];
                if (CVT) {
                    af[mt][0] = f2tf(x0); af[mt][1] = f2tf(x1);
                    af[mt][2] = f2tf(x2); af[mt][3] = f2tf(x3);
                } else {
                    af[mt][0] = __float_as_uint(x0); af[mt][1] = __float_as_uint(x1);
                    af[mt][2] = __float_as_uint(x2); af[mt][3] = __float_as_uint(x3);
                }
            }
            #pragma unroll
            for (int nt = 0; nt < 4; nt++) {
                const float* base = Bb + (kk * 8 + tg) * BS_ST + wc * 32 + nt * 8 + g;
                float y0 = base[0];
                float y1 = base[4 * BS_ST];
                if (CVT) {
                    bf[nt][0] = f2tf(y0); bf[nt][1] = f2tf(y1);
                } else {
                    bf[nt][0] = __float_as_uint(y0); bf[nt][1] = __float_as_uint(y1);
                }
            }
            #pragma unroll
            for (int mt = 0; mt < 4; mt++)
                #pragma unroll
                for (int nt = 0; nt < 4; nt++)
                    mma_tf32(acc[mt][nt], af[mt], bf[nt]);
        }
    }

    int rowBase = blockIdx.y * BM;
    int colBase = blockIdx.x * BN;
    #pragma unroll
    for (int mt = 0; mt < 4; mt++) {
        int r0 = rowBase + wr * 64 + mt * 16 + g;
        int r1 = r0 + 8;
        float b0 = 0.f, b1 = 0.f;
        if (EPI) {
            int p = r0 & (NPB - 1);
            int rel = (p >> 7) - (p & 127);
            rel = (rel < -7 ? -7 : (rel > 7 ? 7 : rel)) + 7;
            b0 = bt[rel];
            p = r1 & (NPB - 1);
            rel = (p >> 7) - (p & 127);
            rel = (rel < -7 ? -7 : (rel > 7 ? 7 : rel)) + 7;
            b1 = bt[rel];
        }
        #pragma unroll
        for (int nt = 0; nt < 4; nt++) {
            int cc = colBase + wc * 32 + nt * 8 + tg * 2;
            float2 v0, v1;
            if (EPI) {
                v0.x = acc[mt][nt][0] + g_bvec[cc]   + b0 * g_wpcol[cc];
                v0.y = acc[mt][nt][1] + g_bvec[cc+1] + b0 * g_wpcol[cc+1];
                v1.x = acc[mt][nt][2] + g_bvec[cc]   + b1 * g_wpcol[cc];
                v1.y = acc[mt][nt][3] + g_bvec[cc+1] + b1 * g_wpcol[cc+1];
            } else {
                v0 = make_float2(acc[mt][nt][0], acc[mt][nt][1]);
                v1 = make_float2(acc[mt][nt][2], acc[mt][nt][3]);
            }
            *(float2*)(C + (size_t)r0 * N + cc) = v0;
            *(float2*)(C + (size_t)r1 * N + cc) = v1;
        }
    }
}

// ---------------- launch ----------------
extern "C" void kernel_launch(void* const* d_in, const int* in_sizes, int n_in,
                              void* d_out, int out_size)
{
    const float* x    = (const float*)d_in[0];
    const float* Wq   = (const float*)d_in[1];
    const float* Wk   = (const float*)d_in[2];
    const float* Wv   = (const float*)d_in[3];
    const float* Wo   = (const float*)d_in[4];
    const float* bo   = (const float*)d_in[5];
    const float* proj = (const float*)d_in[6];
    const float* Wp   = (const float*)d_in[7];
    const float* bp   = (const float*)d_in[8];
    const float* bt   = (const float*)d_in[9];
    float* out = (float*)d_out;

    cudaFuncSetAttribute(mma_gemm_kernel<0, false>, cudaFuncAttributeMaxDynamicSharedMemorySize, GEMM_SMEM);
    cudaFuncSetAttribute(mma_gemm_kernel<1, true>,  cudaFuncAttributeMaxDynamicSharedMemorySize, GEMM_SMEM);
    cudaFuncSetAttribute(kctx_kernel2,  cudaFuncAttributeMaxDynamicSharedMemorySize, K2_SMEM);
    cudaFuncSetAttribute(qattn_kernel,  cudaFuncAttributeMaxDynamicSharedMemorySize, Q_SMEM);

    float *qkv_p, *wqkv_p, *attn_p, *wowp_p;
    cudaGetSymbolAddress((void**)&qkv_p,  g_qkv);
    cudaGetSymbolAddress((void**)&wqkv_p, g_Wqkv);
    cudaGetSymbolAddress((void**)&attn_p, g_attn);
    cudaGetSymbolAddress((void**)&wowp_p, g_WoWp);

    prep_kernel<<<INNER + 1, 256>>>(Wo, bo, Wp, bp);
    projprep_kernel<<<DH, NBF>>>(proj);
    pack_wqkv_kernel<<<C_, 512>>>(Wq, Wk, Wv);

    mma_gemm_kernel<0, false><<<dim3(QKVN / BN, NTOT / BM), 256, GEMM_SMEM>>>(
        x, wqkv_p, qkv_p, QKVN, C_, nullptr);

    kctx_kernel2<<<dim3(KSPLITS, BH), 512, K2_SMEM>>>();
    reduce2_kernel<<<(BH * NBF * DH) / 256, 256>>>();
    qattn_kernel<<<dim3(NPB / 128, BH), 512, Q_SMEM>>>();

    mma_gemm_kernel<1, true><<<dim3(C_ / BN, NTOT / BM), 256, GEMM_SMEM>>>(
        attn_p, wowp_p, out, C_, INNER, bt);
}

// round 7
// speedup vs baseline: 1.0380x; 1.0380x over previous
#include <cuda_runtime.h>
#include <math.h>
#include <stdint.h>

#define NPB    16384
#define NTOT   65536
#define C_     256
#define INNER  512
#define QKVN   1536
#define HEADS  8
#define DH     64
#define NBF    256
#define BH     32
#define EPS_   1e-4f
#define DN_    0.3535533905932738f
#define RATIO_ 0.0625f
#define KSPLITS 32
#define NEG_INF_ -3.0e38f

// ---------------- scratch ----------------
__device__ float g_qkv [(size_t)NTOT * QKVN];
__device__ float g_Wqkv[(size_t)C_ * QKVN];
__device__ float g_projT[DH * NBF];
__device__ float g_kmax[BH];
__device__ float g_pctx [(size_t)BH * KSPLITS * NBF * DH];
__device__ float g_pksum[(size_t)BH * KSPLITS * 2 * NBF];
__device__ float g_pvsum[(size_t)BH * KSPLITS * DH];
__device__ float g_ctx  [(size_t)BH * NBF * DH];
__device__ float g_ksum [(size_t)BH * NBF];
__device__ float g_attn[(size_t)NTOT * INNER];
__device__ float g_WoWp[(size_t)INNER * C_];
__device__ float g_bvec[C_];
__device__ float g_wpcol[C_];

static __device__ __forceinline__ void atomicMaxFloat(float* addr, float val) {
    int* ia = (int*)addr;
    int old = *ia;
    while (__int_as_float(old) < val) {
        int assumed = old;
        old = atomicCAS(ia, assumed, __float_as_int(val));
        if (old == assumed) break;
    }
}

// ---------------- prep ----------------
__global__ __launch_bounds__(256) void prep_kernel(
    const float* __restrict__ Wo, const float* __restrict__ bo,
    const float* __restrict__ Wp, const float* __restrict__ bp)
{
    int i = blockIdx.x, j = threadIdx.x;
    if (i < INNER) {
        __shared__ float wrow[C_];
        wrow[j] = Wo[i * C_ + j];
        __syncthreads();
        float s = 0.f;
        #pragma unroll 8
        for (int c = 0; c < C_; c++) s += wrow[c] * Wp[c * C_ + j];
        g_WoWp[i * C_ + j] = s;
    } else {
        float s = 0.f, w = 0.f;
        for (int c = 0; c < C_; c++) { float wp = Wp[c * C_ + j]; s += bo[c] * wp; w += wp; }
        g_bvec[j]  = s + bp[j];
        g_wpcol[j] = w;
        if (j < BH) g_kmax[j] = NEG_INF_;
    }
}

__global__ void projprep_kernel(const float* __restrict__ proj) {
    int d = blockIdx.x, f = threadIdx.x;
    g_projT[d * NBF + f] = proj[f * DH + d] * DN_;
}

__global__ __launch_bounds__(512) void pack_wqkv_kernel(
    const float* __restrict__ Wq, const float* __restrict__ Wk, const float* __restrict__ Wv)
{
    int i = blockIdx.x;
    int j = threadIdx.x;
    g_Wqkv[(size_t)i * QKVN + j]        = Wq[(size_t)i * INNER + j];
    g_Wqkv[(size_t)i * QKVN + 512 + j]  = Wk[(size_t)i * INNER + j];
    g_Wqkv[(size_t)i * QKVN + 1024 + j] = Wv[(size_t)i * INNER + j];
}

// ==================== common MMA helpers ====================
static __device__ __forceinline__ void cp_async16(float* s, const float* g) {
    unsigned saddr = (unsigned)__cvta_generic_to_shared(s);
    asm volatile("cp.async.cg.shared.global [%0], [%1], 16;\n" :: "r"(saddr), "l"(g));
}
#define CP_COMMIT() asm volatile("cp.async.commit_group;\n")
#define CP_WAIT0()  asm volatile("cp.async.wait_group 0;\n")

static __device__ __forceinline__ uint32_t f2tf(float x) {
    uint32_t r; asm("cvt.rna.tf32.f32 %0, %1;" : "=r"(r) : "f"(x)); return r;
}
static __device__ __forceinline__ void mma_tf32(float* c, const uint32_t* a, const uint32_t* b) {
    asm volatile("mma.sync.aligned.m16n8k8.row.col.f32.tf32.tf32.f32 "
        "{%0,%1,%2,%3},{%4,%5,%6,%7},{%8,%9},{%0,%1,%2,%3};"
        : "+f"(c[0]), "+f"(c[1]), "+f"(c[2]), "+f"(c[3])
        : "r"(a[0]), "r"(a[1]), "r"(a[2]), "r"(a[3]), "r"(b[0]), "r"(b[1]));
}

#define PJ_ST 264
#define AT_ST 68
#define VT_ST 72
#define KP_ST 76
#define QP_ST 260
#define CX_ST 72

static __device__ __forceinline__ void load_projT_s(float* ps, int t) {
    #pragma unroll
    for (int i = 0; i < 16; i++) {
        int idx = t + i * 256;
        int r = idx >> 6, c4 = (idx & 63) * 4;
        cp_async16(&ps[r * PJ_ST + c4], g_projT + r * 256 + c4);
    }
}
template<int ST>
static __device__ __forceinline__ void load_tile64(float* s, int b, int h, int n0, int off, int t) {
    #pragma unroll
    for (int i = 0; i < 4; i++) {
        int idx = t + i * 256;
        int r = idx >> 4, c4 = (idx & 15) * 4;
        cp_async16(&s[r * ST + c4],
            g_qkv + (size_t)(b * NPB + n0 + r) * QKVN + off + h * DH + c4);
    }
}

// dd[n][f] = tile @ projT : M=64 (2 warps x32), N=256 (4 warps x64), K=64
static __device__ __forceinline__ void mma_dd(
    const float* __restrict__ As, const float* __restrict__ Ps,
    float acc[2][8][4], int warpM, int warpN, int g, int tg)
{
    #pragma unroll
    for (int kk = 0; kk < 8; kk++) {
        uint32_t af[2][4], bf[8][2];
        #pragma unroll
        for (int mt = 0; mt < 2; mt++) {
            const float* a = As + (warpM * 32 + mt * 16 + g) * AT_ST + kk * 8 + tg;
            af[mt][0] = f2tf(a[0]);
            af[mt][1] = f2tf(a[8 * AT_ST]);
            af[mt][2] = f2tf(a[4]);
            af[mt][3] = f2tf(a[8 * AT_ST + 4]);
        }
        #pragma unroll
        for (int nt = 0; nt < 8; nt++) {
            const float* bp_ = Ps + (kk * 8 + tg) * PJ_ST + warpN * 64 + nt * 8 + g;
            bf[nt][0] = f2tf(bp_[0]);
            bf[nt][1] = f2tf(bp_[4 * PJ_ST]);
        }
        #pragma unroll
        for (int mt = 0; mt < 2; mt++)
            #pragma unroll
            for (int nt = 0; nt < 8; nt++)
                mma_tf32(acc[mt][nt], af[mt], bf[nt]);
    }
}

// ==================== K2: key features -> partial (unscaled) ctx/ksum + max + vsum ====
#define K2_SMEM ((64*PJ_ST + 2*64*AT_ST + 2*64*VT_ST + 256*KP_ST + 64 + 256) * 4)
__global__ __launch_bounds__(256, 1) void kctx_kernel2()
{
    extern __shared__ float sm[];
    float* Ps    = sm;
    float* Ks    = Ps + 64 * PJ_ST;          // 2 buffers
    float* Vs    = Ks + 2 * 64 * AT_ST;      // 2 buffers
    float* KPs   = Vs + 2 * 64 * VT_ST;
    float* sdiag = KPs + 256 * KP_ST;
    float* red   = sdiag + 64;
    int t = threadIdx.x;
    int bh = blockIdx.y, b = bh >> 3, h = bh & 7;
    int sp = blockIdx.x;
    int warp = t >> 5, lane = t & 31, g = lane >> 2, tg = lane & 3;
    int warpM = warp >> 2, warpN = warp & 3;
    int warpM2 = warp >> 1, warpN2 = warp & 1;

    load_projT_s(Ps, t);
    float acc2[4][4][4];
    #pragma unroll
    for (int a = 0; a < 4; a++)
        #pragma unroll
        for (int bq = 0; bq < 4; bq++)
            #pragma unroll
            for (int r = 0; r < 4; r++) acc2[a][bq][r] = 0.f;
    float ksacc[8][2];
    #pragma unroll
    for (int nt = 0; nt < 8; nt++) { ksacc[nt][0] = 0.f; ksacc[nt][1] = 0.f; }
    float tmax = NEG_INF_;
    float vsum_acc = 0.f;

    load_tile64<AT_ST>(Ks, b, h, sp * 512, 512, t);
    load_tile64<VT_ST>(Vs, b, h, sp * 512, 1024, t);
    CP_COMMIT();

    for (int c = 0; c < 8; c++) {
        CP_WAIT0();
        __syncthreads();
        float* Kb = Ks + (c & 1) * 64 * AT_ST;
        float* Vb = Vs + (c & 1) * 64 * VT_ST;
        if (c + 1 < 8) {
            int n1 = sp * 512 + (c + 1) * 64;
            load_tile64<AT_ST>(Ks + ((c + 1) & 1) * 64 * AT_ST, b, h, n1, 512, t);
            load_tile64<VT_ST>(Vs + ((c + 1) & 1) * 64 * VT_ST, b, h, n1, 1024, t);
            CP_COMMIT();
        }
        if (t < 64) {
            float s = 0.f, vs = 0.f;
            #pragma unroll 8
            for (int r = 0; r < 64; r++) {
                float kv = Kb[t * AT_ST + r];
                s += kv * kv;
                vs += Vb[r * VT_ST + t];
            }
            sdiag[t] = 0.5f * s * (DN_ * DN_);
            vsum_acc += vs;
        }

        float acc[2][8][4];
        #pragma unroll
        for (int mt = 0; mt < 2; mt++)
            #pragma unroll
            for (int nt = 0; nt < 8; nt++)
                #pragma unroll
                for (int r = 0; r < 4; r++) acc[mt][nt][r] = 0.f;
        mma_dd(Kb, Ps, acc, warpM, warpN, g, tg);
        __syncthreads();    // sdiag visible

        float s0a[8], s1a[8];
        #pragma unroll
        for (int nt = 0; nt < 8; nt++) { s0a[nt] = 0.f; s1a[nt] = 0.f; }
        #pragma unroll
        for (int mt = 0; mt < 2; mt++) {
            int n_a = warpM * 32 + mt * 16 + g;
            int n_b = n_a + 8;
            float da = sdiag[n_a], db = sdiag[n_b];
            #pragma unroll
            for (int nt = 0; nt < 8; nt++) {
                int f0 = warpN * 64 + nt * 8 + tg * 2;
                float d0 = acc[mt][nt][0], d1 = acc[mt][nt][1];
                float d2 = acc[mt][nt][2], d3 = acc[mt][nt][3];
                tmax = fmaxf(tmax, fmaxf(fmaxf(d0, d1), fmaxf(d2, d3)));
                float k0 = __expf(d0 - da);
                float k1 = __expf(d1 - da);
                float k2 = __expf(d2 - db);
                float k3 = __expf(d3 - db);
                KPs[f0 * KP_ST + n_a]       = k0;
                KPs[(f0 + 1) * KP_ST + n_a] = k1;
                KPs[f0 * KP_ST + n_b]       = k2;
                KPs[(f0 + 1) * KP_ST + n_b] = k3;
                s0a[nt] += k0 + k2;
                s1a[nt] += k1 + k3;
            }
        }
        #pragma unroll
        for (int nt = 0; nt < 8; nt++) {
            float s0 = s0a[nt], s1 = s1a[nt];
            #pragma unroll
            for (int o = 4; o <= 16; o <<= 1) {
                s0 += __shfl_xor_sync(0xffffffffu, s0, o);
                s1 += __shfl_xor_sync(0xffffffffu, s1, o);
            }
            ksacc[nt][0] += s0; ksacc[nt][1] += s1;
        }
        __syncthreads();    // KPs visible

        #pragma unroll
        for (int kk = 0; kk < 8; kk++) {
            uint32_t af[4][4], bf[4][2];
            #pragma unroll
            for (int mt2 = 0; mt2 < 4; mt2++) {
                const float* a = KPs + (warpM2 * 64 + mt2 * 16 + g) * KP_ST + kk * 8 + tg;
                af[mt2][0] = f2tf(a[0]);
                af[mt2][1] = f2tf(a[8 * KP_ST]);
                af[mt2][2] = f2tf(a[4]);
                af[mt2][3] = f2tf(a[8 * KP_ST + 4]);
            }
            #pragma unroll
            for (int nt2 = 0; nt2 < 4; nt2++) {
                const float* bp_ = Vb + (kk * 8 + tg) * VT_ST + warpN2 * 32 + nt2 * 8 + g;
                bf[nt2][0] = f2tf(bp_[0]);
                bf[nt2][1] = f2tf(bp_[4 * VT_ST]);
            }
            #pragma unroll
            for (int mt2 = 0; mt2 < 4; mt2++)
                #pragma unroll
                for (int nt2 = 0; nt2 < 4; nt2++)
                    mma_tf32(acc2[mt2][nt2], af[mt2], bf[nt2]);
        }
    }

    red[t] = tmax; __syncthreads();
    for (int s = 128; s > 0; s >>= 1) {
        if (t < s) red[t] = fmaxf(red[t], red[t + s]);
        __syncthreads();
    }
    if (t == 0) atomicMaxFloat(&g_kmax[bh], red[0]);

    float* outp = g_pctx + ((size_t)bh * KSPLITS + sp) * NBF * DH;
    #pragma unroll
    for (int mt2 = 0; mt2 < 4; mt2++) {
        int f = warpM2 * 64 + mt2 * 16 + g;
        #pragma unroll
        for (int nt2 = 0; nt2 < 4; nt2++) {
            int d = warpN2 * 32 + nt2 * 8 + tg * 2;
            *(float2*)(outp + (size_t)f * DH + d)       = make_float2(acc2[mt2][nt2][0], acc2[mt2][nt2][1]);
            *(float2*)(outp + (size_t)(f + 8) * DH + d) = make_float2(acc2[mt2][nt2][2], acc2[mt2][nt2][3]);
        }
    }
    if (g == 0) {
        float* kout = g_pksum + (((size_t)bh * KSPLITS + sp) * 2 + warpM) * NBF;
        #pragma unroll
        for (int nt = 0; nt < 8; nt++) {
            int f0 = warpN * 64 + nt * 8 + tg * 2;
            kout[f0]     = ksacc[nt][0];
            kout[f0 + 1] = ksacc[nt][1];
        }
    }
    if (t < 64) g_pvsum[((size_t)bh * KSPLITS + sp) * DH + t] = vsum_acc;
}

// ---------------- deterministic reduction with rescale + EPS terms ----------------
__global__ __launch_bounds__(256) void reduce2_kernel()
{
    int idx = blockIdx.x * 256 + threadIdx.x;
    int bh = idx >> 14;
    int rem = idx & 16383;
    int d = rem & 63;
    float m = g_kmax[bh];
    float sc = RATIO_ * __expf(-m);
    float s = 0.f;
    const float* base = g_pctx + (size_t)bh * KSPLITS * NBF * DH + rem;
    #pragma unroll 8
    for (int sp = 0; sp < KSPLITS; sp++) s += base[(size_t)sp * NBF * DH];
    float vs = 0.f;
    const float* vb = g_pvsum + (size_t)bh * KSPLITS * DH + d;
    #pragma unroll 8
    for (int sp = 0; sp < KSPLITS; sp++) vs += vb[sp * DH];
    g_ctx[idx] = sc * s + (RATIO_ * EPS_) * vs;
    if (idx < BH * NBF) {
        int bh2 = idx >> 8, f = idx & 255;
        float m2 = g_kmax[bh2];
        float s2 = 0.f;
        const float* kb = g_pksum + (size_t)bh2 * KSPLITS * 2 * NBF + f;
        for (int j = 0; j < KSPLITS * 2; j++) s2 += kb[j * NBF];
        g_ksum[idx] = RATIO_ * __expf(-m2) * s2 + (RATIO_ * EPS_) * (float)NPB;
    }
}

// ==================== Q: fused query features + attention (256 rows / block) ====
#define Q_SMEM ((64*PJ_ST + 256*CX_ST + 64*AT_ST + 64*QP_ST + 256 + 64 + 256 + 64) * 4)
__global__ __launch_bounds__(256, 1) void qattn_kernel()
{
    extern __shared__ float sm[];
    float* Ps   = sm;
    float* Cs   = Ps + 64 * PJ_ST;
    float* Qs   = Cs + 256 * CX_ST;
    float* QPs  = Qs + 64 * AT_ST;
    float* sks  = QPs + 64 * QP_ST;
    float* sdq  = sks + 256;
    float* rowr = sdq + 64;
    float* srow = rowr + 256;
    int t = threadIdx.x;
    int bh = blockIdx.y, b = bh >> 3, h = bh & 7;
    int warp = t >> 5, lane = t & 31, g = lane >> 2, tg = lane & 3;
    int warpM = warp >> 2, warpN = warp & 3;

    load_projT_s(Ps, t);
    #pragma unroll
    for (int i = 0; i < 16; i++) {
        int idx = t + i * 256;
        int r = idx >> 4, c4 = (idx & 15) * 4;
        cp_async16(&Cs[r * CX_ST + c4], g_ctx + (size_t)bh * NBF * DH + r * DH + c4);
    }
    sks[t] = g_ksum[bh * NBF + t];

    for (int c = 0; c < 4; c++) {
        int n0 = blockIdx.x * 256 + c * 64;
        load_tile64<AT_ST>(Qs, b, h, n0, 0, t);
        CP_COMMIT(); CP_WAIT0();
        __syncthreads();
        if (t < 64) {
            float s = 0.f;
            #pragma unroll
            for (int d = 0; d < 64; d++) { float qv = Qs[t * AT_ST + d]; s += qv * qv; }
            sdq[t] = 0.5f * s * (DN_ * DN_);
        }
        __syncthreads();

        float acc[2][8][4];
        #pragma unroll
        for (int mt = 0; mt < 2; mt++)
            #pragma unroll
            for (int nt = 0; nt < 8; nt++)
                #pragma unroll
                for (int r = 0; r < 4; r++) acc[mt][nt][r] = 0.f;
        mma_dd(Qs, Ps, acc, warpM, warpN, g, tg);

        #pragma unroll
        for (int mt = 0; mt < 2; mt++) {
            float r0m = NEG_INF_, r1m = NEG_INF_;
            #pragma unroll
            for (int nt = 0; nt < 8; nt++) {
                r0m = fmaxf(r0m, fmaxf(acc[mt][nt][0], acc[mt][nt][1]));
                r1m = fmaxf(r1m, fmaxf(acc[mt][nt][2], acc[mt][nt][3]));
            }
            r0m = fmaxf(r0m, __shfl_xor_sync(0xffffffffu, r0m, 1));
            r0m = fmaxf(r0m, __shfl_xor_sync(0xffffffffu, r0m, 2));
            r1m = fmaxf(r1m, __shfl_xor_sync(0xffffffffu, r1m, 1));
            r1m = fmaxf(r1m, __shfl_xor_sync(0xffffffffu, r1m, 2));
            if (tg == 0) {
                int n_a = warpM * 32 + mt * 16 + g;
                rowr[warpN * 64 + n_a]     = r0m;
                rowr[warpN * 64 + n_a + 8] = r1m;
            }
        }
        __syncthreads();
        if (t < 64)
            srow[t] = fmaxf(fmaxf(rowr[t], rowr[64 + t]), fmaxf(rowr[128 + t], rowr[192 + t]));
        __syncthreads();

        #pragma unroll
        for (int mt = 0; mt < 2; mt++) {
            int n_a = warpM * 32 + mt * 16 + g;
            int n_b = n_a + 8;
            float oa = sdq[n_a] + srow[n_a], ob = sdq[n_b] + srow[n_b];
            float d0 = 0.f, d1 = 0.f;
            #pragma unroll
            for (int nt = 0; nt < 8; nt++) {
                int f0 = warpN * 64 + nt * 8 + tg * 2;
                float q0 = RATIO_ * (__expf(acc[mt][nt][0] - oa) + EPS_);
                float q1 = RATIO_ * (__expf(acc[mt][nt][1] - oa) + EPS_);
                float q2 = RATIO_ * (__expf(acc[mt][nt][2] - ob) + EPS_);
                float q3 = RATIO_ * (__expf(acc[mt][nt][3] - ob) + EPS_);
                acc[mt][nt][0] = q0; acc[mt][nt][1] = q1;
                acc[mt][nt][2] = q2; acc[mt][nt][3] = q3;
                float ks0 = sks[f0], ks1 = sks[f0 + 1];
                d0 += q0 * ks0 + q1 * ks1;
                d1 += q2 * ks0 + q3 * ks1;
            }
            d0 += __shfl_xor_sync(0xffffffffu, d0, 1);
            d0 += __shfl_xor_sync(0xffffffffu, d0, 2);
            d1 += __shfl_xor_sync(0xffffffffu, d1, 1);
            d1 += __shfl_xor_sync(0xffffffffu, d1, 2);
            if (tg == 0) {
                rowr[warpN * 64 + n_a] = d0;
                rowr[warpN * 64 + n_b] = d1;
            }
        }
        __syncthreads();
        if (t < 64)
            srow[t] = 1.0f / (rowr[t] + rowr[64 + t] + rowr[128 + t] + rowr[192 + t]);
        __syncthreads();

        #pragma unroll
        for (int mt = 0; mt < 2; mt++) {
            int n_a = warpM * 32 + mt * 16 + g;
            int n_b = n_a + 8;
            float ia = srow[n_a], ib = srow[n_b];
            #pragma unroll
            for (int nt = 0; nt < 8; nt++) {
                int f0 = warpN * 64 + nt * 8 + tg * 2;
                QPs[n_a * QP_ST + f0]     = acc[mt][nt][0] * ia;
                QPs[n_a * QP_ST + f0 + 1] = acc[mt][nt][1] * ia;
                QPs[n_b * QP_ST + f0]     = acc[mt][nt][2] * ib;
                QPs[n_b * QP_ST + f0 + 1] = acc[mt][nt][3] * ib;
            }
        }
        __syncthreads();

        float acc3[2][2][4];
        #pragma unroll
        for (int mt3 = 0; mt3 < 2; mt3++)
            #pragma unroll
            for (int nt3 = 0; nt3 < 2; nt3++)
                #pragma unroll
                for (int r = 0; r < 4; r++) acc3[mt3][nt3][r] = 0.f;
        #pragma unroll 4
        for (int kk = 0; kk < 32; kk++) {
            uint32_t af[2][4], bf[2][2];
            #pragma unroll
            for (int mt3 = 0; mt3 < 2; mt3++) {
                const float* a = QPs + (warpM * 32 + mt3 * 16 + g) * QP_ST + kk * 8 + tg;
                af[mt3][0] = f2tf(a[0]);
                af[mt3][1] = f2tf(a[8 * QP_ST]);
                af[mt3][2] = f2tf(a[4]);
                af[mt3][3] = f2tf(a[8 * QP_ST + 4]);
            }
            #pragma unroll
            for (int nt3 = 0; nt3 < 2; nt3++) {
                const float* bp_ = Cs + (kk * 8 + tg) * CX_ST + warpN * 16 + nt3 * 8 + g;
                bf[nt3][0] = f2tf(bp_[0]);
                bf[nt3][1] = f2tf(bp_[4 * CX_ST]);
            }
            #pragma unroll
            for (int mt3 = 0; mt3 < 2; mt3++)
                #pragma unroll
                for (int nt3 = 0; nt3 < 2; nt3++)
                    mma_tf32(acc3[mt3][nt3], af[mt3], bf[nt3]);
        }
        float* ob2 = g_attn + (size_t)(b * NPB + n0) * INNER + h * DH;
        #pragma unroll
        for (int mt3 = 0; mt3 < 2; mt3++) {
            int n = warpM * 32 + mt3 * 16 + g;
            #pragma unroll
            for (int nt3 = 0; nt3 < 2; nt3++) {
                int d = warpN * 16 + nt3 * 8 + tg * 2;
                *(float2*)(ob2 + (size_t)n * INNER + d)       = make_float2(acc3[mt3][nt3][0], acc3[mt3][nt3][1]);
                *(float2*)(ob2 + (size_t)(n + 8) * INNER + d) = make_float2(acc3[mt3][nt3][2], acc3[mt3][nt3][3]);
            }
        }
        __syncthreads();
    }
}

// ==================== TF32 MMA GEMM (3-stage pipeline) ====================
#define BM 128
#define BN 128
#define BKT 32
#define AS_ST 36
#define BS_ST 136
#define GEMM_SMEM ((3*BM*AS_ST + 3*BKT*BS_ST) * 4)

template<int CVT, bool EPI>
__global__ __launch_bounds__(256, 2) void mma_gemm_kernel(
    const float* __restrict__ A, const float* __restrict__ B, float* __restrict__ C,
    int N, int K, const float* __restrict__ bt)
{
    extern __shared__ float smem[];
    float* As = smem;
    float* Bs = smem + 3 * BM * AS_ST;

    int tid = threadIdx.x;
    int lane = tid & 31, warp = tid >> 5;
    int wr = warp >> 2, wc = warp & 3;
    int g = lane >> 2, tg = lane & 3;

    float acc[4][4][4];
    #pragma unroll
    for (int mt = 0; mt < 4; mt++)
        #pragma unroll
        for (int nt = 0; nt < 4; nt++)
            #pragma unroll
            for (int r = 0; r < 4; r++) acc[mt][nt][r] = 0.f;

    const float* Abase = A + (size_t)blockIdx.y * BM * K;
    const float* Bbase = B + (size_t)blockIdx.x * BN;

    auto load_tile = [&](int kt, int buf) {
        const float* Ag = Abase + kt * BKT;
        #pragma unroll
        for (int i = 0; i < 4; i++) {
            int idx = tid + i * 256;
            int row = idx >> 3, c4 = (idx & 7) * 4;
            cp_async16(&As[buf * BM * AS_ST + row * AS_ST + c4], Ag + (size_t)row * K + c4);
        }
        const float* Bg = Bbase + (size_t)(kt * BKT) * N;
        #pragma unroll
        for (int i = 0; i < 4; i++) {
            int idx = tid + i * 256;
            int row = idx >> 5, c4 = (idx & 31) * 4;
            cp_async16(&Bs[buf * BKT * BS_ST + row * BS_ST + c4], Bg + (size_t)row * N + c4);
        }
        CP_COMMIT();
    };

    int KT = K / BKT;
    load_tile(0, 0);
    load_tile(1, 1);

    for (int kt = 0; kt < KT; kt++) {
        if (kt + 1 < KT) { asm volatile("cp.async.wait_group 1;\n"); }
        else             { asm volatile("cp.async.wait_group 0;\n"); }
        __syncthreads();
        if (kt + 2 < KT) load_tile(kt + 2, (kt + 2) % 3);

        const float* Ab = &As[(kt % 3) * BM * AS_ST];
        const float* Bb = &Bs[(kt % 3) * BKT * BS_ST];

        #pragma unroll
        for (int kk = 0; kk < 4; kk++) {
            uint32_t af[4][4], bf[4][2];
            #pragma unroll
            for (int mt = 0; mt < 4; mt++) {
                const float* base = Ab + (wr * 64 + mt * 16 + g) * AS_ST + kk * 8 + tg;
                float x0 = base[0];
                float x1 = base[8 * AS_ST];
                float x2 = base[4];
                float x3 = base[8 * AS_ST + 4];
                if (CVT) {
                    af[mt][0] = f2tf(x0); af[mt][1] = f2tf(x1);
                    af[mt][2] = f2tf(x2); af[mt][3] = f2tf(x3);
                } else {
                    af[mt][0] = __float_as_uint(x0); af[mt][1] = __float_as_uint(x1);
                    af[mt][2] = __float_as_uint(x2); af[mt][3] = __float_as_uint(x3);
                }
            }
            #pragma unroll
            for (int nt = 0; nt < 4; nt++) {
                const float* base = Bb + (kk * 8 + tg) * BS_ST + wc * 32 + nt * 8 + g;
                float y0 = base[0];
                float y1 = base[4 * BS_ST];
                if (CVT) {
                    bf[nt][0] = f2tf(y0); bf[nt][1] = f2tf(y1);
                } else {
                    bf[nt][0] = __float_as_uint(y0); bf[nt][1] = __float_as_uint(y1);
                }
            }
            #pragma unroll
            for (int mt = 0; mt < 4; mt++)
                #pragma unroll
                for (int nt = 0; nt < 4; nt++)
                    mma_tf32(acc[mt][nt], af[mt], bf[nt]);
        }
    }

    int rowBase = blockIdx.y * BM;
    int colBase = blockIdx.x * BN;
    #pragma unroll
    for (int mt = 0; mt < 4; mt++) {
        int r0 = rowBase + wr * 64 + mt * 16 + g;
        int r1 = r0 + 8;
        float b0 = 0.f, b1 = 0.f;
        if (EPI) {
            int p = r0 & (NPB - 1);
            int rel = (p >> 7) - (p & 127);
            rel = (rel < -7 ? -7 : (rel > 7 ? 7 : rel)) + 7;
            b0 = bt[rel];
            p = r1 & (NPB - 1);
            rel = (p >> 7) - (p & 127);
            rel = (rel < -7 ? -7 : (rel > 7 ? 7 : rel)) + 7;
            b1 = bt[rel];
        }
        #pragma unroll
        for (int nt = 0; nt < 4; nt++) {
            int cc = colBase + wc * 32 + nt * 8 + tg * 2;
            float2 v0, v1;
            if (EPI) {
                v0.x = acc[mt][nt][0] + g_bvec[cc]   + b0 * g_wpcol[cc];
                v0.y = acc[mt][nt][1] + g_bvec[cc+1] + b0 * g_wpcol[cc+1];
                v1.x = acc[mt][nt][2] + g_bvec[cc]   + b1 * g_wpcol[cc];
                v1.y = acc[mt][nt][3] + g_bvec[cc+1] + b1 * g_wpcol[cc+1];
            } else {
                v0 = make_float2(acc[mt][nt][0], acc[mt][nt][1]);
                v1 = make_float2(acc[mt][nt][2], acc[mt][nt][3]);
            }
            *(float2*)(C + (size_t)r0 * N + cc) = v0;
            *(float2*)(C + (size_t)r1 * N + cc) = v1;
        }
    }
}

// ---------------- launch ----------------
extern "C" void kernel_launch(void* const* d_in, const int* in_sizes, int n_in,
                              void* d_out, int out_size)
{
    const float* x    = (const float*)d_in[0];
    const float* Wq   = (const float*)d_in[1];
    const float* Wk   = (const float*)d_in[2];
    const float* Wv   = (const float*)d_in[3];
    const float* Wo   = (const float*)d_in[4];
    const float* bo   = (const float*)d_in[5];
    const float* proj = (const float*)d_in[6];
    const float* Wp   = (const float*)d_in[7];
    const float* bp   = (const float*)d_in[8];
    const float* bt   = (const float*)d_in[9];
    float* out = (float*)d_out;

    cudaFuncSetAttribute(mma_gemm_kernel<0, false>, cudaFuncAttributeMaxDynamicSharedMemorySize, GEMM_SMEM);
    cudaFuncSetAttribute(mma_gemm_kernel<1, true>,  cudaFuncAttributeMaxDynamicSharedMemorySize, GEMM_SMEM);
    cudaFuncSetAttribute(kctx_kernel2,  cudaFuncAttributeMaxDynamicSharedMemorySize, K2_SMEM);
    cudaFuncSetAttribute(qattn_kernel,  cudaFuncAttributeMaxDynamicSharedMemorySize, Q_SMEM);

    float *qkv_p, *wqkv_p, *attn_p, *wowp_p;
    cudaGetSymbolAddress((void**)&qkv_p,  g_qkv);
    cudaGetSymbolAddress((void**)&wqkv_p, g_Wqkv);
    cudaGetSymbolAddress((void**)&attn_p, g_attn);
    cudaGetSymbolAddress((void**)&wowp_p, g_WoWp);

    prep_kernel<<<INNER + 1, 256>>>(Wo, bo, Wp, bp);
    projprep_kernel<<<DH, NBF>>>(proj);
    pack_wqkv_kernel<<<C_, 512>>>(Wq, Wk, Wv);

    mma_gemm_kernel<0, false><<<dim3(QKVN / BN, NTOT / BM), 256, GEMM_SMEM>>>(
        x, wqkv_p, qkv_p, QKVN, C_, nullptr);

    kctx_kernel2<<<dim3(KSPLITS, BH), 256, K2_SMEM>>>();
    reduce2_kernel<<<(BH * NBF * DH) / 256, 256>>>();
    qattn_kernel<<<dim3(NPB / 256, BH), 256, Q_SMEM>>>();

    mma_gemm_kernel<1, true><<<dim3(C_ / BN, NTOT / BM), 256, GEMM_SMEM>>>(
        attn_p, wowp_p, out, C_, INNER, bt);
}

// round 11
// speedup vs baseline: 1.0646x; 1.0257x over previous
#include <cuda_runtime.h>
#include <math.h>
#include <stdint.h>

#define NPB    16384
#define NTOT   65536
#define C_     256
#define INNER  512
#define QKVN   1536
#define HEADS  8
#define DH     64
#define NBF    256
#define BH     32
#define EPS_   1e-4f
#define DN_    0.3535533905932738f
#define RATIO_ 0.0625f
#define KSPLITS 32
#define NEG_INF_ -3.0e38f

// ---------------- scratch ----------------
__device__ float g_qkv [(size_t)NTOT * QKVN];
__device__ float g_Wqkv[(size_t)C_ * QKVN];
__device__ float g_projT[DH * NBF];
__device__ float g_kmax[BH];
__device__ float g_pctx [(size_t)BH * KSPLITS * NBF * DH];
__device__ float g_pksum[(size_t)BH * KSPLITS * 2 * NBF];
__device__ float g_pvsum[(size_t)BH * KSPLITS * DH];
__device__ float g_ctx  [(size_t)BH * NBF * DH];
__device__ float g_ksum [(size_t)BH * NBF];
__device__ float g_attn[(size_t)NTOT * INNER];
__device__ float g_WoWp[(size_t)INNER * C_];
__device__ float g_bvec[C_];
__device__ float g_wpcol[C_];

static __device__ __forceinline__ void atomicMaxFloat(float* addr, float val) {
    int* ia = (int*)addr;
    int old = *ia;
    while (__int_as_float(old) < val) {
        int assumed = old;
        old = atomicCAS(ia, assumed, __float_as_int(val));
        if (old == assumed) break;
    }
}

// ---------------- prep ----------------
__global__ __launch_bounds__(256) void prep_kernel(
    const float* __restrict__ Wo, const float* __restrict__ bo,
    const float* __restrict__ Wp, const float* __restrict__ bp)
{
    int i = blockIdx.x, j = threadIdx.x;
    if (i < INNER) {
        __shared__ float wrow[C_];
        wrow[j] = Wo[i * C_ + j];
        __syncthreads();
        float s = 0.f;
        #pragma unroll 8
        for (int c = 0; c < C_; c++) s += wrow[c] * Wp[c * C_ + j];
        g_WoWp[i * C_ + j] = s;
    } else {
        float s = 0.f, w = 0.f;
        for (int c = 0; c < C_; c++) { float wp = Wp[c * C_ + j]; s += bo[c] * wp; w += wp; }
        g_bvec[j]  = s + bp[j];
        g_wpcol[j] = w;
        if (j < BH) g_kmax[j] = NEG_INF_;
    }
}

__global__ void projprep_kernel(const float* __restrict__ proj) {
    int d = blockIdx.x, f = threadIdx.x;
    g_projT[d * NBF + f] = proj[f * DH + d] * DN_;
}

__global__ __launch_bounds__(512) void pack_wqkv_kernel(
    const float* __restrict__ Wq, const float* __restrict__ Wk, const float* __restrict__ Wv)
{
    int i = blockIdx.x;
    int j = threadIdx.x;
    g_Wqkv[(size_t)i * QKVN + j]        = Wq[(size_t)i * INNER + j];
    g_Wqkv[(size_t)i * QKVN + 512 + j]  = Wk[(size_t)i * INNER + j];
    g_Wqkv[(size_t)i * QKVN + 1024 + j] = Wv[(size_t)i * INNER + j];
}

// ==================== common MMA helpers ====================
static __device__ __forceinline__ void cp_async16(float* s, const float* g) {
    unsigned saddr = (unsigned)__cvta_generic_to_shared(s);
    asm volatile("cp.async.cg.shared.global [%0], [%1], 16;\n" :: "r"(saddr), "l"(g));
}
#define CP_COMMIT() asm volatile("cp.async.commit_group;\n")
#define CP_WAIT0()  asm volatile("cp.async.wait_group 0;\n")

static __device__ __forceinline__ uint32_t f2tf(float x) {
    uint32_t r; asm("cvt.rna.tf32.f32 %0, %1;" : "=r"(r) : "f"(x)); return r;
}
static __device__ __forceinline__ void mma_tf32(float* c, const uint32_t* a, const uint32_t* b) {
    asm volatile("mma.sync.aligned.m16n8k8.row.col.f32.tf32.tf32.f32 "
        "{%0,%1,%2,%3},{%4,%5,%6,%7},{%8,%9},{%0,%1,%2,%3};"
        : "+f"(c[0]), "+f"(c[1]), "+f"(c[2]), "+f"(c[3])
        : "r"(a[0]), "r"(a[1]), "r"(a[2]), "r"(a[3]), "r"(b[0]), "r"(b[1]));
}

#define PJ_ST 264
#define AT_ST 68
#define VT_ST 72
#define KP_ST 76
#define QP_ST 260
#define CX_ST 72

static __device__ __forceinline__ void load_projT_s(float* ps, int t) {
    #pragma unroll
    for (int i = 0; i < 16; i++) {
        int idx = t + i * 256;
        int r = idx >> 6, c4 = (idx & 63) * 4;
        cp_async16(&ps[r * PJ_ST + c4], g_projT + r * 256 + c4);
    }
}
template<int ST>
static __device__ __forceinline__ void load_tile64(float* s, int b, int h, int n0, int off, int t) {
    #pragma unroll
    for (int i = 0; i < 4; i++) {
        int idx = t + i * 256;
        int r = idx >> 4, c4 = (idx & 15) * 4;
        cp_async16(&s[r * ST + c4],
            g_qkv + (size_t)(b * NPB + n0 + r) * QKVN + off + h * DH + c4);
    }
}

// dd[n][f] = tile @ projT : M=64 (2 warps x32), N=256 (4 warps x64), K=64
static __device__ __forceinline__ void mma_dd(
    const float* __restrict__ As, const float* __restrict__ Ps,
    float acc[2][8][4], int warpM, int warpN, int g, int tg)
{
    #pragma unroll
    for (int kk = 0; kk < 8; kk++) {
        uint32_t af[2][4], bf[8][2];
        #pragma unroll
        for (int mt = 0; mt < 2; mt++) {
            const float* a = As + (warpM * 32 + mt * 16 + g) * AT_ST + kk * 8 + tg;
            af[mt][0] = f2tf(a[0]);
            af[mt][1] = f2tf(a[8 * AT_ST]);
            af[mt][2] = f2tf(a[4]);
            af[mt][3] = f2tf(a[8 * AT_ST + 4]);
        }
        #pragma unroll
        for (int nt = 0; nt < 8; nt++) {
            const float* bp_ = Ps + (kk * 8 + tg) * PJ_ST + warpN * 64 + nt * 8 + g;
            bf[nt][0] = f2tf(bp_[0]);
            bf[nt][1] = f2tf(bp_[4 * PJ_ST]);
        }
        #pragma unroll
        for (int mt = 0; mt < 2; mt++)
            #pragma unroll
            for (int nt = 0; nt < 8; nt++)
                mma_tf32(acc[mt][nt], af[mt], bf[nt]);
    }
}

// ==================== K2: key features -> partial (unscaled) ctx/ksum + max + vsum ====
#define K2_SMEM ((64*PJ_ST + 2*64*AT_ST + 2*64*VT_ST + 256*KP_ST + 64 + 256) * 4)
__global__ __launch_bounds__(256, 1) void kctx_kernel2()
{
    extern __shared__ float sm[];
    float* Ps    = sm;
    float* Ks    = Ps + 64 * PJ_ST;          // 2 buffers
    float* Vs    = Ks + 2 * 64 * AT_ST;      // 2 buffers
    float* KPs   = Vs + 2 * 64 * VT_ST;
    float* sdiag = KPs + 256 * KP_ST;
    float* red   = sdiag + 64;
    int t = threadIdx.x;
    int bh = blockIdx.y, b = bh >> 3, h = bh & 7;
    int sp = blockIdx.x;
    int warp = t >> 5, lane = t & 31, g = lane >> 2, tg = lane & 3;
    int warpM = warp >> 2, warpN = warp & 3;
    int warpM2 = warp >> 1, warpN2 = warp & 1;
    int prow = t >> 2, pq = t & 3;    // parallel-reduction mapping: 4 threads per row/col

    load_projT_s(Ps, t);
    float acc2[4][4][4];
    #pragma unroll
    for (int a = 0; a < 4; a++)
        #pragma unroll
        for (int bq = 0; bq < 4; bq++)
            #pragma unroll
            for (int r = 0; r < 4; r++) acc2[a][bq][r] = 0.f;
    float ksacc[8][2];
    #pragma unroll
    for (int nt = 0; nt < 8; nt++) { ksacc[nt][0] = 0.f; ksacc[nt][1] = 0.f; }
    float tmax = NEG_INF_;
    float vsum_acc = 0.f;    // per-thread partial (prow=col, pq=row-quarter)

    load_tile64<AT_ST>(Ks, b, h, sp * 512, 512, t);
    load_tile64<VT_ST>(Vs, b, h, sp * 512, 1024, t);
    CP_COMMIT();

    for (int c = 0; c < 8; c++) {
        CP_WAIT0();
        __syncthreads();
        float* Kb = Ks + (c & 1) * 64 * AT_ST;
        float* Vb = Vs + (c & 1) * 64 * VT_ST;
        if (c + 1 < 8) {
            int n1 = sp * 512 + (c + 1) * 64;
            load_tile64<AT_ST>(Ks + ((c + 1) & 1) * 64 * AT_ST, b, h, n1, 512, t);
            load_tile64<VT_ST>(Vs + ((c + 1) & 1) * 64 * VT_ST, b, h, n1, 1024, t);
            CP_COMMIT();
        }
        // parallel sdiag (K row sums of squares) + vsum (V col sums): all 256 threads
        {
            const float4* kr = (const float4*)(Kb + prow * AT_ST + pq * 16);
            float s = 0.f;
            #pragma unroll
            for (int j = 0; j < 4; j++) {
                float4 v = kr[j];
                s += v.x * v.x + v.y * v.y + v.z * v.z + v.w * v.w;
            }
            s += __shfl_xor_sync(0xffffffffu, s, 1);
            s += __shfl_xor_sync(0xffffffffu, s, 2);
            if (pq == 0) sdiag[prow] = 0.5f * s * (DN_ * DN_);
            float vsp = 0.f;
            #pragma unroll
            for (int i = 0; i < 16; i++) {
                int r = pq * 16 + ((i + pq) & 15);   // rotation avoids 4-way bank conflict
                vsp += Vb[r * VT_ST + prow];
            }
            vsum_acc += vsp;
        }

        float acc[2][8][4];
        #pragma unroll
        for (int mt = 0; mt < 2; mt++)
            #pragma unroll
            for (int nt = 0; nt < 8; nt++)
                #pragma unroll
                for (int r = 0; r < 4; r++) acc[mt][nt][r] = 0.f;
        mma_dd(Kb, Ps, acc, warpM, warpN, g, tg);
        __syncthreads();    // sdiag visible

        float s0a[8], s1a[8];
        #pragma unroll
        for (int nt = 0; nt < 8; nt++) { s0a[nt] = 0.f; s1a[nt] = 0.f; }
        #pragma unroll
        for (int mt = 0; mt < 2; mt++) {
            int n_a = warpM * 32 + mt * 16 + g;
            int n_b = n_a + 8;
            float da = sdiag[n_a], db = sdiag[n_b];
            #pragma unroll
            for (int nt = 0; nt < 8; nt++) {
                int f0 = warpN * 64 + nt * 8 + tg * 2;
                float d0 = acc[mt][nt][0], d1 = acc[mt][nt][1];
                float d2 = acc[mt][nt][2], d3 = acc[mt][nt][3];
                tmax = fmaxf(tmax, fmaxf(fmaxf(d0, d1), fmaxf(d2, d3)));
                float k0 = __expf(d0 - da);
                float k1 = __expf(d1 - da);
                float k2 = __expf(d2 - db);
                float k3 = __expf(d3 - db);
                KPs[f0 * KP_ST + n_a]       = k0;
                KPs[(f0 + 1) * KP_ST + n_a] = k1;
                KPs[f0 * KP_ST + n_b]       = k2;
                KPs[(f0 + 1) * KP_ST + n_b] = k3;
                s0a[nt] += k0 + k2;
                s1a[nt] += k1 + k3;
            }
        }
        #pragma unroll
        for (int nt = 0; nt < 8; nt++) {
            float s0 = s0a[nt], s1 = s1a[nt];
            #pragma unroll
            for (int o = 4; o <= 16; o <<= 1) {
                s0 += __shfl_xor_sync(0xffffffffu, s0, o);
                s1 += __shfl_xor_sync(0xffffffffu, s1, o);
            }
            ksacc[nt][0] += s0; ksacc[nt][1] += s1;
        }
        __syncthreads();    // KPs visible

        #pragma unroll
        for (int kk = 0; kk < 8; kk++) {
            uint32_t af[4][4], bf[4][2];
            #pragma unroll
            for (int mt2 = 0; mt2 < 4; mt2++) {
                const float* a = KPs + (warpM2 * 64 + mt2 * 16 + g) * KP_ST + kk * 8 + tg;
                af[mt2][0] = f2tf(a[0]);
                af[mt2][1] = f2tf(a[8 * KP_ST]);
                af[mt2][2] = f2tf(a[4]);
                af[mt2][3] = f2tf(a[8 * KP_ST + 4]);
            }
            #pragma unroll
            for (int nt2 = 0; nt2 < 4; nt2++) {
                const float* bp_ = Vb + (kk * 8 + tg) * VT_ST + warpN2 * 32 + nt2 * 8 + g;
                bf[nt2][0] = f2tf(bp_[0]);
                bf[nt2][1] = f2tf(bp_[4 * VT_ST]);
            }
            #pragma unroll
            for (int mt2 = 0; mt2 < 4; mt2++)
                #pragma unroll
                for (int nt2 = 0; nt2 < 4; nt2++)
                    mma_tf32(acc2[mt2][nt2], af[mt2], bf[nt2]);
        }
    }

    red[t] = tmax; __syncthreads();
    for (int s = 128; s > 0; s >>= 1) {
        if (t < s) red[t] = fmaxf(red[t], red[t + s]);
        __syncthreads();
    }
    if (t == 0) atomicMaxFloat(&g_kmax[bh], red[0]);

    float* outp = g_pctx + ((size_t)bh * KSPLITS + sp) * NBF * DH;
    #pragma unroll
    for (int mt2 = 0; mt2 < 4; mt2++) {
        int f = warpM2 * 64 + mt2 * 16 + g;
        #pragma unroll
        for (int nt2 = 0; nt2 < 4; nt2++) {
            int d = warpN2 * 32 + nt2 * 8 + tg * 2;
            *(float2*)(outp + (size_t)f * DH + d)       = make_float2(acc2[mt2][nt2][0], acc2[mt2][nt2][1]);
            *(float2*)(outp + (size_t)(f + 8) * DH + d) = make_float2(acc2[mt2][nt2][2], acc2[mt2][nt2][3]);
        }
    }
    if (g == 0) {
        float* kout = g_pksum + (((size_t)bh * KSPLITS + sp) * 2 + warpM) * NBF;
        #pragma unroll
        for (int nt = 0; nt < 8; nt++) {
            int f0 = warpN * 64 + nt * 8 + tg * 2;
            kout[f0]     = ksacc[nt][0];
            kout[f0 + 1] = ksacc[nt][1];
        }
    }
    // combine vsum partials (4 threads per column) and write
    vsum_acc += __shfl_xor_sync(0xffffffffu, vsum_acc, 1);
    vsum_acc += __shfl_xor_sync(0xffffffffu, vsum_acc, 2);
    if (pq == 0) g_pvsum[((size_t)bh * KSPLITS + sp) * DH + prow] = vsum_acc;
}

// ---------------- deterministic reduction with rescale + EPS terms ----------------
__global__ __launch_bounds__(256) void reduce2_kernel()
{
    int idx = blockIdx.x * 256 + threadIdx.x;
    int bh = idx >> 14;
    int rem = idx & 16383;
    int d = rem & 63;
    float m = g_kmax[bh];
    float sc = RATIO_ * __expf(-m);
    float s = 0.f;
    const float* base = g_pctx + (size_t)bh * KSPLITS * NBF * DH + rem;
    #pragma unroll 8
    for (int sp = 0; sp < KSPLITS; sp++) s += base[(size_t)sp * NBF * DH];
    float vs = 0.f;
    const float* vb = g_pvsum + (size_t)bh * KSPLITS * DH + d;
    #pragma unroll 8
    for (int sp = 0; sp < KSPLITS; sp++) vs += vb[sp * DH];
    g_ctx[idx] = sc * s + (RATIO_ * EPS_) * vs;
    if (idx < BH * NBF) {
        int bh2 = idx >> 8, f = idx & 255;
        float m2 = g_kmax[bh2];
        float s2 = 0.f;
        const float* kb = g_pksum + (size_t)bh2 * KSPLITS * 2 * NBF + f;
        for (int j = 0; j < KSPLITS * 2; j++) s2 += kb[j * NBF];
        g_ksum[idx] = RATIO_ * __expf(-m2) * s2 + (RATIO_ * EPS_) * (float)NPB;
    }
}

// ==================== Q: fused query features + attention (256 rows / block,
//                      register-staged Q prefetch) ====
#define Q_SMEM ((64*PJ_ST + 256*CX_ST + 64*AT_ST + 64*QP_ST + 256 + 64 + 256 + 64) * 4)
__global__ __launch_bounds__(256, 1) void qattn_kernel()
{
    extern __shared__ float sm[];
    float* Ps   = sm;
    float* Cs   = Ps + 64 * PJ_ST;
    float* Qs   = Cs + 256 * CX_ST;
    float* QPs  = Qs + 64 * AT_ST;
    float* sks  = QPs + 64 * QP_ST;
    float* sdq  = sks + 256;
    float* rowr = sdq + 64;
    float* srow = rowr + 256;
    int t = threadIdx.x;
    int bh = blockIdx.y, b = bh >> 3, h = bh & 7;
    int warp = t >> 5, lane = t & 31, g = lane >> 2, tg = lane & 3;
    int warpM = warp >> 2, warpN = warp & 3;

    load_projT_s(Ps, t);
    #pragma unroll
    for (int i = 0; i < 16; i++) {
        int idx = t + i * 256;
        int r = idx >> 4, c4 = (idx & 15) * 4;
        cp_async16(&Cs[r * CX_ST + c4], g_ctx + (size_t)bh * NBF * DH + r * DH + c4);
    }
    sks[t] = g_ksum[bh * NBF + t];
    load_tile64<AT_ST>(Qs, b, h, blockIdx.x * 256, 0, t);
    CP_COMMIT();

    for (int c = 0; c < 4; c++) {
        int n0 = blockIdx.x * 256 + c * 64;
        if (c == 0) { CP_WAIT0(); __syncthreads(); }

        // register prefetch of next Q chunk (latency hidden behind dd MMA)
        float4 qreg[4];
        if (c < 3) {
            int n1 = blockIdx.x * 256 + (c + 1) * 64;
            #pragma unroll
            for (int i = 0; i < 4; i++) {
                int idx = t + i * 256;
                int r = idx >> 4, c4 = (idx & 15) * 4;
                qreg[i] = *(const float4*)(g_qkv + (size_t)(b * NPB + n1 + r) * QKVN + h * DH + c4);
            }
        }

        if (t < 64) {
            float s = 0.f;
            #pragma unroll
            for (int d = 0; d < 64; d++) { float qv = Qs[t * AT_ST + d]; s += qv * qv; }
            sdq[t] = 0.5f * s * (DN_ * DN_);
        }
        __syncthreads();

        float acc[2][8][4];
        #pragma unroll
        for (int mt = 0; mt < 2; mt++)
            #pragma unroll
            for (int nt = 0; nt < 8; nt++)
                #pragma unroll
                for (int r = 0; r < 4; r++) acc[mt][nt][r] = 0.f;
        mma_dd(Qs, Ps, acc, warpM, warpN, g, tg);

        #pragma unroll
        for (int mt = 0; mt < 2; mt++) {
            float r0m = NEG_INF_, r1m = NEG_INF_;
            #pragma unroll
            for (int nt = 0; nt < 8; nt++) {
                r0m = fmaxf(r0m, fmaxf(acc[mt][nt][0], acc[mt][nt][1]));
                r1m = fmaxf(r1m, fmaxf(acc[mt][nt][2], acc[mt][nt][3]));
            }
            r0m = fmaxf(r0m, __shfl_xor_sync(0xffffffffu, r0m, 1));
            r0m = fmaxf(r0m, __shfl_xor_sync(0xffffffffu, r0m, 2));
            r1m = fmaxf(r1m, __shfl_xor_sync(0xffffffffu, r1m, 1));
            r1m = fmaxf(r1m, __shfl_xor_sync(0xffffffffu, r1m, 2));
            if (tg == 0) {
                int n_a = warpM * 32 + mt * 16 + g;
                rowr[warpN * 64 + n_a]     = r0m;
                rowr[warpN * 64 + n_a + 8] = r1m;
            }
        }
        __syncthreads();    // all warps past mma_dd -> Qs dead; safe to overwrite

        // store prefetched next chunk into Qs (no reads of Qs until next iteration)
        if (c < 3) {
            #pragma unroll
            for (int i = 0; i < 4; i++) {
                int idx = t + i * 256;
                int r = idx >> 4, c4 = (idx & 15) * 4;
                *(float4*)(&Qs[r * AT_ST + c4]) = qreg[i];
            }
        }

        if (t < 64)
            srow[t] = fmaxf(fmaxf(rowr[t], rowr[64 + t]), fmaxf(rowr[128 + t], rowr[192 + t]));
        __syncthreads();

        #pragma unroll
        for (int mt = 0; mt < 2; mt++) {
            int n_a = warpM * 32 + mt * 16 + g;
            int n_b = n_a + 8;
            float oa = sdq[n_a] + srow[n_a], ob = sdq[n_b] + srow[n_b];
            float d0 = 0.f, d1 = 0.f;
            #pragma unroll
            for (int nt = 0; nt < 8; nt++) {
                int f0 = warpN * 64 + nt * 8 + tg * 2;
                float q0 = RATIO_ * (__expf(acc[mt][nt][0] - oa) + EPS_);
                float q1 = RATIO_ * (__expf(acc[mt][nt][1] - oa) + EPS_);
                float q2 = RATIO_ * (__expf(acc[mt][nt][2] - ob) + EPS_);
                float q3 = RATIO_ * (__expf(acc[mt][nt][3] - ob) + EPS_);
                acc[mt][nt][0] = q0; acc[mt][nt][1] = q1;
                acc[mt][nt][2] = q2; acc[mt][nt][3] = q3;
                float ks0 = sks[f0], ks1 = sks[f0 + 1];
                d0 += q0 * ks0 + q1 * ks1;
                d1 += q2 * ks0 + q3 * ks1;
            }
            d0 += __shfl_xor_sync(0xffffffffu, d0, 1);
            d0 += __shfl_xor_sync(0xffffffffu, d0, 2);
            d1 += __shfl_xor_sync(0xffffffffu, d1, 1);
            d1 += __shfl_xor_sync(0xffffffffu, d1, 2);
            if (tg == 0) {
                rowr[warpN * 64 + n_a] = d0;
                rowr[warpN * 64 + n_b] = d1;
            }
        }
        __syncthreads();
        if (t < 64)
            srow[t] = 1.0f / (rowr[t] + rowr[64 + t] + rowr[128 + t] + rowr[192 + t]);
        __syncthreads();

        #pragma unroll
        for (int mt = 0; mt < 2; mt++) {
            int n_a = warpM * 32 + mt * 16 + g;
            int n_b = n_a + 8;
            float ia = srow[n_a], ib = srow[n_b];
            #pragma unroll
            for (int nt = 0; nt < 8; nt++) {
                int f0 = warpN * 64 + nt * 8 + tg * 2;
                QPs[n_a * QP_ST + f0]     = acc[mt][nt][0] * ia;
                QPs[n_a * QP_ST + f0 + 1] = acc[mt][nt][1] * ia;
                QPs[n_b * QP_ST + f0]     = acc[mt][nt][2] * ib;
                QPs[n_b * QP_ST + f0 + 1] = acc[mt][nt][3] * ib;
            }
        }
        __syncthreads();

        float acc3[2][2][4];
        #pragma unroll
        for (int mt3 = 0; mt3 < 2; mt3++)
            #pragma unroll
            for (int nt3 = 0; nt3 < 2; nt3++)
                #pragma unroll
                for (int r = 0; r < 4; r++) acc3[mt3][nt3][r] = 0.f;
        #pragma unroll 4
        for (int kk = 0; kk < 32; kk++) {
            uint32_t af[2][4], bf[2][2];
            #pragma unroll
            for (int mt3 = 0; mt3 < 2; mt3++) {
                const float* a = QPs + (warpM * 32 + mt3 * 16 + g) * QP_ST + kk * 8 + tg;
                af[mt3][0] = f2tf(a[0]);
                af[mt3][1] = f2tf(a[8 * QP_ST]);
                af[mt3][2] = f2tf(a[4]);
                af[mt3][3] = f2tf(a[8 * QP_ST + 4]);
            }
            #pragma unroll
            for (int nt3 = 0; nt3 < 2; nt3++) {
                const float* bp_ = Cs + (kk * 8 + tg) * CX_ST + warpN * 16 + nt3 * 8 + g;
                bf[nt3][0] = f2tf(bp_[0]);
                bf[nt3][1] = f2tf(bp_[4 * CX_ST]);
            }
            #pragma unroll
            for (int mt3 = 0; mt3 < 2; mt3++)
                #pragma unroll
                for (int nt3 = 0; nt3 < 2; nt3++)
                    mma_tf32(acc3[mt3][nt3], af[mt3], bf[nt3]);
        }
        float* ob2 = g_attn + (size_t)(b * NPB + n0) * INNER + h * DH;
        #pragma unroll
        for (int mt3 = 0; mt3 < 2; mt3++) {
            int n = warpM * 32 + mt3 * 16 + g;
            #pragma unroll
            for (int nt3 = 0; nt3 < 2; nt3++) {
                int d = warpN * 16 + nt3 * 8 + tg * 2;
                *(float2*)(ob2 + (size_t)n * INNER + d)       = make_float2(acc3[mt3][nt3][0], acc3[mt3][nt3][1]);
                *(float2*)(ob2 + (size_t)(n + 8) * INNER + d) = make_float2(acc3[mt3][nt3][2], acc3[mt3][nt3][3]);
            }
        }
        __syncthreads();
    }
}

// ==================== TF32 MMA GEMM (3-stage pipeline) ====================
#define BM 128
#define BN 128
#define BKT 32
#define AS_ST 36
#define BS_ST 136
#define GEMM_SMEM ((3*BM*AS_ST + 3*BKT*BS_ST) * 4)

template<int CVT, bool EPI>
__global__ __launch_bounds__(256, 2) void mma_gemm_kernel(
    const float* __restrict__ A, const float* __restrict__ B, float* __restrict__ C,
    int N, int K, const float* __restrict__ bt)
{
    extern __shared__ float smem[];
    float* As = smem;
    float* Bs = smem + 3 * BM * AS_ST;

    int tid = threadIdx.x;
    int lane = tid & 31, warp = tid >> 5;
    int wr = warp >> 2, wc = warp & 3;
    int g = lane >> 2, tg = lane & 3;

    float acc[4][4][4];
    #pragma unroll
    for (int mt = 0; mt < 4; mt++)
        #pragma unroll
        for (int nt = 0; nt < 4; nt++)
            #pragma unroll
            for (int r = 0; r < 4; r++) acc[mt][nt][r] = 0.f;

    const float* Abase = A + (size_t)blockIdx.y * BM * K;
    const float* Bbase = B + (size_t)blockIdx.x * BN;

    auto load_tile = [&](int kt, int buf) {
        const float* Ag = Abase + kt * BKT;
        #pragma unroll
        for (int i = 0; i < 4; i++) {
            int idx = tid + i * 256;
            int row = idx >> 3, c4 = (idx & 7) * 4;
            cp_async16(&As[buf * BM * AS_ST + row * AS_ST + c4], Ag + (size_t)row * K + c4);
        }
        const float* Bg = Bbase + (size_t)(kt * BKT) * N;
        #pragma unroll
        for (int i = 0; i < 4; i++) {
            int idx = tid + i * 256;
            int row = idx >> 5, c4 = (idx & 31) * 4;
            cp_async16(&Bs[buf * BKT * BS_ST + row * BS_ST + c4], Bg + (size_t)row * N + c4);
        }
        CP_COMMIT();
    };

    int KT = K / BKT;
    load_tile(0, 0);
    load_tile(1, 1);

    for (int kt = 0; kt < KT; kt++) {
        if (kt + 1 < KT) { asm volatile("cp.async.wait_group 1;\n"); }
        else             { asm volatile("cp.async.wait_group 0;\n"); }
        __syncthreads();
        if (kt + 2 < KT) load_tile(kt + 2, (kt + 2) % 3);

        const float* Ab = &As[(kt % 3) * BM * AS_ST];
        const float* Bb = &Bs[(kt % 3) * BKT * BS_ST];

        #pragma unroll
        for (int kk = 0; kk < 4; kk++) {
            uint32_t af[4][4], bf[4][2];
            #pragma unroll
            for (int mt = 0; mt < 4; mt++) {
                const float* base = Ab + (wr * 64 + mt * 16 + g) * AS_ST + kk * 8 + tg;
                float x0 = base[0];
                float x1 = base[8 * AS_ST];
                float x2 = base[4];
                float x3 = base[8 * AS_ST + 4];
                if (CVT) {
                    af[mt][0] = f2tf(x0); af[mt][1] = f2tf(x1);
                    af[mt][2] = f2tf(x2); af[mt][3] = f2tf(x3);
                } else {
                    af[mt][0] = __float_as_uint(x0); af[mt][1] = __float_as_uint(x1);
                    af[mt][2] = __float_as_uint(x2); af[mt][3] = __float_as_uint(x3);
                }
            }
            #pragma unroll
            for (int nt = 0; nt < 4; nt++) {
                const float* base = Bb + (kk * 8 + tg) * BS_ST + wc * 32 + nt * 8 + g;
                float y0 = base[0];
                float y1 = base[4 * BS_ST];
                if (CVT) {
                    bf[nt][0] = f2tf(y0); bf[nt][1] = f2tf(y1);
                } else {
                    bf[nt][0] = __float_as_uint(y0); bf[nt][1] = __float_as_uint(y1);
                }
            }
            #pragma unroll
            for (int mt = 0; mt < 4; mt++)
                #pragma unroll
                for (int nt = 0; nt < 4; nt++)
                    mma_tf32(acc[mt][nt], af[mt], bf[nt]);
        }
    }

    int rowBase = blockIdx.y * BM;
    int colBase = blockIdx.x * BN;
    #pragma unroll
    for (int mt = 0; mt < 4; mt++) {
        int r0 = rowBase + wr * 64 + mt * 16 + g;
        int r1 = r0 + 8;
        float b0 = 0.f, b1 = 0.f;
        if (EPI) {
            int p = r0 & (NPB - 1);
            int rel = (p >> 7) - (p & 127);
            rel = (rel < -7 ? -7 : (rel > 7 ? 7 : rel)) + 7;
            b0 = bt[rel];
            p = r1 & (NPB - 1);
            rel = (p >> 7) - (p & 127);
            rel = (rel < -7 ? -7 : (rel > 7 ? 7 : rel)) + 7;
            b1 = bt[rel];
        }
        #pragma unroll
        for (int nt = 0; nt < 4; nt++) {
            int cc = colBase + wc * 32 + nt * 8 + tg * 2;
            float2 v0, v1;
            if (EPI) {
                v0.x = acc[mt][nt][0] + g_bvec[cc]   + b0 * g_wpcol[cc];
                v0.y = acc[mt][nt][1] + g_bvec[cc+1] + b0 * g_wpcol[cc+1];
                v1.x = acc[mt][nt][2] + g_bvec[cc]   + b1 * g_wpcol[cc];
                v1.y = acc[mt][nt][3] + g_bvec[cc+1] + b1 * g_wpcol[cc+1];
            } else {
                v0 = make_float2(acc[mt][nt][0], acc[mt][nt][1]);
                v1 = make_float2(acc[mt][nt][2], acc[mt][nt][3]);
            }
            *(float2*)(C + (size_t)r0 * N + cc) = v0;
            *(float2*)(C + (size_t)r1 * N + cc) = v1;
        }
    }
}

// ---------------- launch ----------------
extern "C" void kernel_launch(void* const* d_in, const int* in_sizes, int n_in,
                              void* d_out, int out_size)
{
    const float* x    = (const float*)d_in[0];
    const float* Wq   = (const float*)d_in[1];
    const float* Wk   = (const float*)d_in[2];
    const float* Wv   = (const float*)d_in[3];
    const float* Wo   = (const float*)d_in[4];
    const float* bo   = (const float*)d_in[5];
    const float* proj = (const float*)d_in[6];
    const float* Wp   = (const float*)d_in[7];
    const float* bp   = (const float*)d_in[8];
    const float* bt   = (const float*)d_in[9];
    float* out = (float*)d_out;

    cudaFuncSetAttribute(mma_gemm_kernel<0, false>, cudaFuncAttributeMaxDynamicSharedMemorySize, GEMM_SMEM);
    cudaFuncSetAttribute(mma_gemm_kernel<1, true>,  cudaFuncAttributeMaxDynamicSharedMemorySize, GEMM_SMEM);
    cudaFuncSetAttribute(kctx_kernel2,  cudaFuncAttributeMaxDynamicSharedMemorySize, K2_SMEM);
    cudaFuncSetAttribute(qattn_kernel,  cudaFuncAttributeMaxDynamicSharedMemorySize, Q_SMEM);

    float *qkv_p, *wqkv_p, *attn_p, *wowp_p;
    cudaGetSymbolAddress((void**)&qkv_p,  g_qkv);
    cudaGetSymbolAddress((void**)&wqkv_p, g_Wqkv);
    cudaGetSymbolAddress((void**)&attn_p, g_attn);
    cudaGetSymbolAddress((void**)&wowp_p, g_WoWp);

    prep_kernel<<<INNER + 1, 256>>>(Wo, bo, Wp, bp);
    projprep_kernel<<<DH, NBF>>>(proj);
    pack_wqkv_kernel<<<C_, 512>>>(Wq, Wk, Wv);

    mma_gemm_kernel<0, false><<<dim3(QKVN / BN, NTOT / BM), 256, GEMM_SMEM>>>(
        x, wqkv_p, qkv_p, QKVN, C_, nullptr);

    kctx_kernel2<<<dim3(KSPLITS, BH), 256, K2_SMEM>>>();
    reduce2_kernel<<<(BH * NBF * DH) / 256, 256>>>();
    qattn_kernel<<<dim3(NPB / 256, BH), 256, Q_SMEM>>>();

    mma_gemm_kernel<1, true><<<dim3(C_ / BN, NTOT / BM), 256, GEMM_SMEM>>>(
        attn_p, wowp_p, out, C_, INNER, bt);
}

// round 13
// speedup vs baseline: 1.0749x; 1.0096x over previous
#include <cuda_runtime.h>
#include <math.h>
#include <stdint.h>

#define NPB    16384
#define NTOT   65536
#define C_     256
#define INNER  512
#define QKVN   1536
#define HEADS  8
#define DH     64
#define NBF    256
#define BH     32
#define EPS_   1e-4f
#define DN_    0.3535533905932738f
#define RATIO_ 0.0625f
#define KSPLITS 32
#define NEG_INF_ -3.0e38f

// ---------------- scratch ----------------
__device__ float g_qkv [(size_t)NTOT * QKVN];
__device__ float g_Wqkv[(size_t)C_ * QKVN];
__device__ float g_projT[DH * NBF];
__device__ float g_kmax[BH];
__device__ float g_pctx [(size_t)BH * KSPLITS * NBF * DH];
__device__ float g_pksum[(size_t)BH * KSPLITS * 2 * NBF];
__device__ float g_pvsum[(size_t)BH * KSPLITS * DH];
__device__ float g_ctx  [(size_t)BH * NBF * DH];
__device__ float g_ksum [(size_t)BH * NBF];
__device__ float g_attn[(size_t)NTOT * INNER];
__device__ float g_WoWp[(size_t)INNER * C_];
__device__ float g_bvec[C_];
__device__ float g_wpcol[C_];

static __device__ __forceinline__ void atomicMaxFloat(float* addr, float val) {
    int* ia = (int*)addr;
    int old = *ia;
    while (__int_as_float(old) < val) {
        int assumed = old;
        old = atomicCAS(ia, assumed, __float_as_int(val));
        if (old == assumed) break;
    }
}

// ---------------- prep ----------------
__global__ __launch_bounds__(256) void prep_kernel(
    const float* __restrict__ Wo, const float* __restrict__ bo,
    const float* __restrict__ Wp, const float* __restrict__ bp)
{
    int i = blockIdx.x, j = threadIdx.x;
    if (i < INNER) {
        __shared__ float wrow[C_];
        wrow[j] = Wo[i * C_ + j];
        __syncthreads();
        float s = 0.f;
        #pragma unroll 8
        for (int c = 0; c < C_; c++) s += wrow[c] * Wp[c * C_ + j];
        g_WoWp[i * C_ + j] = s;
    } else {
        float s = 0.f, w = 0.f;
        for (int c = 0; c < C_; c++) { float wp = Wp[c * C_ + j]; s += bo[c] * wp; w += wp; }
        g_bvec[j]  = s + bp[j];
        g_wpcol[j] = w;
        if (j < BH) g_kmax[j] = NEG_INF_;
    }
}

__global__ void projprep_kernel(const float* __restrict__ proj) {
    int d = blockIdx.x, f = threadIdx.x;
    g_projT[d * NBF + f] = proj[f * DH + d] * DN_;
}

__global__ __launch_bounds__(512) void pack_wqkv_kernel(
    const float* __restrict__ Wq, const float* __restrict__ Wk, const float* __restrict__ Wv)
{
    int i = blockIdx.x;
    int j = threadIdx.x;
    g_Wqkv[(size_t)i * QKVN + j]        = Wq[(size_t)i * INNER + j];
    g_Wqkv[(size_t)i * QKVN + 512 + j]  = Wk[(size_t)i * INNER + j];
    g_Wqkv[(size_t)i * QKVN + 1024 + j] = Wv[(size_t)i * INNER + j];
}

// ==================== common MMA helpers ====================
static __device__ __forceinline__ void cp_async16(float* s, const float* g) {
    unsigned saddr = (unsigned)__cvta_generic_to_shared(s);
    asm volatile("cp.async.cg.shared.global [%0], [%1], 16;\n" :: "r"(saddr), "l"(g));
}
#define CP_COMMIT() asm volatile("cp.async.commit_group;\n")
#define CP_WAIT0()  asm volatile("cp.async.wait_group 0;\n")

static __device__ __forceinline__ uint32_t f2tf(float x) {
    uint32_t r; asm("cvt.rna.tf32.f32 %0, %1;" : "=r"(r) : "f"(x)); return r;
}
static __device__ __forceinline__ void mma_tf32(float* c, const uint32_t* a, const uint32_t* b) {
    asm volatile("mma.sync.aligned.m16n8k8.row.col.f32.tf32.tf32.f32 "
        "{%0,%1,%2,%3},{%4,%5,%6,%7},{%8,%9},{%0,%1,%2,%3};"
        : "+f"(c[0]), "+f"(c[1]), "+f"(c[2]), "+f"(c[3])
        : "r"(a[0]), "r"(a[1]), "r"(a[2]), "r"(a[3]), "r"(b[0]), "r"(b[1]));
}

#define PJ_ST 264
#define AT_ST 68
#define VT_ST 72
#define KP_ST 76
#define QP_ST 260
#define CX_ST 72

static __device__ __forceinline__ void load_projT_s(float* ps, int t) {
    #pragma unroll
    for (int i = 0; i < 16; i++) {
        int idx = t + i * 256;
        int r = idx >> 6, c4 = (idx & 63) * 4;
        cp_async16(&ps[r * PJ_ST + c4], g_projT + r * 256 + c4);
    }
}
template<int ST>
static __device__ __forceinline__ void load_tile64(float* s, int b, int h, int n0, int off, int t) {
    #pragma unroll
    for (int i = 0; i < 4; i++) {
        int idx = t + i * 256;
        int r = idx >> 4, c4 = (idx & 15) * 4;
        cp_async16(&s[r * ST + c4],
            g_qkv + (size_t)(b * NPB + n0 + r) * QKVN + off + h * DH + c4);
    }
}

// dd[n][f] = tile @ projT : M=64 (2 warps x32), N=256 (4 warps x64), K=64
static __device__ __forceinline__ void mma_dd(
    const float* __restrict__ As, const float* __restrict__ Ps,
    float acc[2][8][4], int warpM, int warpN, int g, int tg)
{
    #pragma unroll
    for (int kk = 0; kk < 8; kk++) {
        uint32_t af[2][4], bf[8][2];
        #pragma unroll
        for (int mt = 0; mt < 2; mt++) {
            const float* a = As + (warpM * 32 + mt * 16 + g) * AT_ST + kk * 8 + tg;
            af[mt][0] = f2tf(a[0]);
            af[mt][1] = f2tf(a[8 * AT_ST]);
            af[mt][2] = f2tf(a[4]);
            af[mt][3] = f2tf(a[8 * AT_ST + 4]);
        }
        #pragma unroll
        for (int nt = 0; nt < 8; nt++) {
            const float* bp_ = Ps + (kk * 8 + tg) * PJ_ST + warpN * 64 + nt * 8 + g;
            bf[nt][0] = f2tf(bp_[0]);
            bf[nt][1] = f2tf(bp_[4 * PJ_ST]);
        }
        #pragma unroll
        for (int mt = 0; mt < 2; mt++)
            #pragma unroll
            for (int nt = 0; nt < 8; nt++)
                mma_tf32(acc[mt][nt], af[mt], bf[nt]);
    }
}

// ==================== K2: key features -> partial (unscaled) ctx/ksum + max + vsum ====
#define K2_SMEM ((64*PJ_ST + 2*64*AT_ST + 2*64*VT_ST + 256*KP_ST + 64 + 256) * 4)
__global__ __launch_bounds__(256, 1) void kctx_kernel2()
{
    extern __shared__ float sm[];
    float* Ps    = sm;
    float* Ks    = Ps + 64 * PJ_ST;
    float* Vs    = Ks + 2 * 64 * AT_ST;
    float* KPs   = Vs + 2 * 64 * VT_ST;
    float* sdiag = KPs + 256 * KP_ST;
    float* red   = sdiag + 64;
    int t = threadIdx.x;
    int bh = blockIdx.y, b = bh >> 3, h = bh & 7;
    int sp = blockIdx.x;
    int warp = t >> 5, lane = t & 31, g = lane >> 2, tg = lane & 3;
    int warpM = warp >> 2, warpN = warp & 3;
    int warpM2 = warp >> 1, warpN2 = warp & 1;
    int prow = t >> 2, pq = t & 3;

    load_projT_s(Ps, t);
    float acc2[4][4][4];
    #pragma unroll
    for (int a = 0; a < 4; a++)
        #pragma unroll
        for (int bq = 0; bq < 4; bq++)
            #pragma unroll
            for (int r = 0; r < 4; r++) acc2[a][bq][r] = 0.f;
    float ksacc[8][2];
    #pragma unroll
    for (int nt = 0; nt < 8; nt++) { ksacc[nt][0] = 0.f; ksacc[nt][1] = 0.f; }
    float tmax = NEG_INF_;
    float vsum_acc = 0.f;

    load_tile64<AT_ST>(Ks, b, h, sp * 512, 512, t);
    load_tile64<VT_ST>(Vs, b, h, sp * 512, 1024, t);
    CP_COMMIT();

    for (int c = 0; c < 8; c++) {
        CP_WAIT0();
        __syncthreads();
        float* Kb = Ks + (c & 1) * 64 * AT_ST;
        float* Vb = Vs + (c & 1) * 64 * VT_ST;
        if (c + 1 < 8) {
            int n1 = sp * 512 + (c + 1) * 64;
            load_tile64<AT_ST>(Ks + ((c + 1) & 1) * 64 * AT_ST, b, h, n1, 512, t);
            load_tile64<VT_ST>(Vs + ((c + 1) & 1) * 64 * VT_ST, b, h, n1, 1024, t);
            CP_COMMIT();
        }
        {
            const float4* kr = (const float4*)(Kb + prow * AT_ST + pq * 16);
            float s = 0.f;
            #pragma unroll
            for (int j = 0; j < 4; j++) {
                float4 v = kr[j];
                s += v.x * v.x + v.y * v.y + v.z * v.z + v.w * v.w;
            }
            s += __shfl_xor_sync(0xffffffffu, s, 1);
            s += __shfl_xor_sync(0xffffffffu, s, 2);
            if (pq == 0) sdiag[prow] = 0.5f * s * (DN_ * DN_);
            float vsp = 0.f;
            #pragma unroll
            for (int i = 0; i < 16; i++) {
                int r = pq * 16 + ((i + pq) & 15);
                vsp += Vb[r * VT_ST + prow];
            }
            vsum_acc += vsp;
        }

        float acc[2][8][4];
        #pragma unroll
        for (int mt = 0; mt < 2; mt++)
            #pragma unroll
            for (int nt = 0; nt < 8; nt++)
                #pragma unroll
                for (int r = 0; r < 4; r++) acc[mt][nt][r] = 0.f;
        mma_dd(Kb, Ps, acc, warpM, warpN, g, tg);
        __syncthreads();

        float s0a[8], s1a[8];
        #pragma unroll
        for (int nt = 0; nt < 8; nt++) { s0a[nt] = 0.f; s1a[nt] = 0.f; }
        #pragma unroll
        for (int mt = 0; mt < 2; mt++) {
            int n_a = warpM * 32 + mt * 16 + g;
            int n_b = n_a + 8;
            float da = sdiag[n_a], db = sdiag[n_b];
            #pragma unroll
            for (int nt = 0; nt < 8; nt++) {
                int f0 = warpN * 64 + nt * 8 + tg * 2;
                float d0 = acc[mt][nt][0], d1 = acc[mt][nt][1];
                float d2 = acc[mt][nt][2], d3 = acc[mt][nt][3];
                tmax = fmaxf(tmax, fmaxf(fmaxf(d0, d1), fmaxf(d2, d3)));
                float k0 = __expf(d0 - da);
                float k1 = __expf(d1 - da);
                float k2 = __expf(d2 - db);
                float k3 = __expf(d3 - db);
                KPs[f0 * KP_ST + n_a]       = k0;
                KPs[(f0 + 1) * KP_ST + n_a] = k1;
                KPs[f0 * KP_ST + n_b]       = k2;
                KPs[(f0 + 1) * KP_ST + n_b] = k3;
                s0a[nt] += k0 + k2;
                s1a[nt] += k1 + k3;
            }
        }
        #pragma unroll
        for (int nt = 0; nt < 8; nt++) {
            float s0 = s0a[nt], s1 = s1a[nt];
            #pragma unroll
            for (int o = 4; o <= 16; o <<= 1) {
                s0 += __shfl_xor_sync(0xffffffffu, s0, o);
                s1 += __shfl_xor_sync(0xffffffffu, s1, o);
            }
            ksacc[nt][0] += s0; ksacc[nt][1] += s1;
        }
        __syncthreads();

        #pragma unroll
        for (int kk = 0; kk < 8; kk++) {
            uint32_t af[4][4], bf[4][2];
            #pragma unroll
            for (int mt2 = 0; mt2 < 4; mt2++) {
                const float* a = KPs + (warpM2 * 64 + mt2 * 16 + g) * KP_ST + kk * 8 + tg;
                af[mt2][0] = f2tf(a[0]);
                af[mt2][1] = f2tf(a[8 * KP_ST]);
                af[mt2][2] = f2tf(a[4]);
                af[mt2][3] = f2tf(a[8 * KP_ST + 4]);
            }
            #pragma unroll
            for (int nt2 = 0; nt2 < 4; nt2++) {
                const float* bp_ = Vb + (kk * 8 + tg) * VT_ST + warpN2 * 32 + nt2 * 8 + g;
                bf[nt2][0] = f2tf(bp_[0]);
                bf[nt2][1] = f2tf(bp_[4 * VT_ST]);
            }
            #pragma unroll
            for (int mt2 = 0; mt2 < 4; mt2++)
                #pragma unroll
                for (int nt2 = 0; nt2 < 4; nt2++)
                    mma_tf32(acc2[mt2][nt2], af[mt2], bf[nt2]);
        }
    }

    red[t] = tmax; __syncthreads();
    for (int s = 128; s > 0; s >>= 1) {
        if (t < s) red[t] = fmaxf(red[t], red[t + s]);
        __syncthreads();
    }
    if (t == 0) atomicMaxFloat(&g_kmax[bh], red[0]);

    float* outp = g_pctx + ((size_t)bh * KSPLITS + sp) * NBF * DH;
    #pragma unroll
    for (int mt2 = 0; mt2 < 4; mt2++) {
        int f = warpM2 * 64 + mt2 * 16 + g;
        #pragma unroll
        for (int nt2 = 0; nt2 < 4; nt2++) {
            int d = warpN2 * 32 + nt2 * 8 + tg * 2;
            *(float2*)(outp + (size_t)f * DH + d)       = make_float2(acc2[mt2][nt2][0], acc2[mt2][nt2][1]);
            *(float2*)(outp + (size_t)(f + 8) * DH + d) = make_float2(acc2[mt2][nt2][2], acc2[mt2][nt2][3]);
        }
    }
    if (g == 0) {
        float* kout = g_pksum + (((size_t)bh * KSPLITS + sp) * 2 + warpM) * NBF;
        #pragma unroll
        for (int nt = 0; nt < 8; nt++) {
            int f0 = warpN * 64 + nt * 8 + tg * 2;
            kout[f0]     = ksacc[nt][0];
            kout[f0 + 1] = ksacc[nt][1];
        }
    }
    vsum_acc += __shfl_xor_sync(0xffffffffu, vsum_acc, 1);
    vsum_acc += __shfl_xor_sync(0xffffffffu, vsum_acc, 2);
    if (pq == 0) g_pvsum[((size_t)bh * KSPLITS + sp) * DH + prow] = vsum_acc;
}

// ---------------- deterministic reduction with rescale + EPS terms ----------------
__global__ __launch_bounds__(256) void reduce2_kernel()
{
    int idx = blockIdx.x * 256 + threadIdx.x;
    int bh = idx >> 14;
    int rem = idx & 16383;
    int d = rem & 63;
    float m = g_kmax[bh];
    float sc = RATIO_ * __expf(-m);
    float s = 0.f;
    const float* base = g_pctx + (size_t)bh * KSPLITS * NBF * DH + rem;
    #pragma unroll 8
    for (int sp = 0; sp < KSPLITS; sp++) s += base[(size_t)sp * NBF * DH];
    float vs = 0.f;
    const float* vb = g_pvsum + (size_t)bh * KSPLITS * DH + d;
    #pragma unroll 8
    for (int sp = 0; sp < KSPLITS; sp++) vs += vb[sp * DH];
    g_ctx[idx] = sc * s + (RATIO_ * EPS_) * vs;
    if (idx < BH * NBF) {
        int bh2 = idx >> 8, f = idx & 255;
        float m2 = g_kmax[bh2];
        float s2 = 0.f;
        const float* kb = g_pksum + (size_t)bh2 * KSPLITS * 2 * NBF + f;
        for (int j = 0; j < KSPLITS * 2; j++) s2 += kb[j * NBF];
        g_ksum[idx] = RATIO_ * __expf(-m2) * s2 + (RATIO_ * EPS_) * (float)NPB;
    }
}

// ==================== Q: fused query features + attention ====================
#define Q_SMEM ((64*PJ_ST + 256*CX_ST + 64*AT_ST + 64*QP_ST + 256 + 64 + 256 + 64) * 4)
__global__ __launch_bounds__(256, 1) void qattn_kernel()
{
    extern __shared__ float sm[];
    float* Ps   = sm;
    float* Cs   = Ps + 64 * PJ_ST;
    float* Qs   = Cs + 256 * CX_ST;
    float* QPs  = Qs + 64 * AT_ST;
    float* sks  = QPs + 64 * QP_ST;
    float* sdq  = sks + 256;
    float* rowr = sdq + 64;
    float* srow = rowr + 256;
    int t = threadIdx.x;
    int bh = blockIdx.y, b = bh >> 3, h = bh & 7;
    int warp = t >> 5, lane = t & 31, g = lane >> 2, tg = lane & 3;
    int warpM = warp >> 2, warpN = warp & 3;

    load_projT_s(Ps, t);
    #pragma unroll
    for (int i = 0; i < 16; i++) {
        int idx = t + i * 256;
        int r = idx >> 4, c4 = (idx & 15) * 4;
        cp_async16(&Cs[r * CX_ST + c4], g_ctx + (size_t)bh * NBF * DH + r * DH + c4);
    }
    sks[t] = g_ksum[bh * NBF + t];
    load_tile64<AT_ST>(Qs, b, h, blockIdx.x * 256, 0, t);
    CP_COMMIT();

    for (int c = 0; c < 4; c++) {
        int n0 = blockIdx.x * 256 + c * 64;
        if (c == 0) { CP_WAIT0(); __syncthreads(); }

        float4 qreg[4];
        if (c < 3) {
            int n1 = blockIdx.x * 256 + (c + 1) * 64;
            #pragma unroll
            for (int i = 0; i < 4; i++) {
                int idx = t + i * 256;
                int r = idx >> 4, c4 = (idx & 15) * 4;
                qreg[i] = *(const float4*)(g_qkv + (size_t)(b * NPB + n1 + r) * QKVN + h * DH + c4);
            }
        }

        if (t < 64) {
            float s = 0.f;
            #pragma unroll
            for (int d = 0; d < 64; d++) { float qv = Qs[t * AT_ST + d]; s += qv * qv; }
            sdq[t] = 0.5f * s * (DN_ * DN_);
        }
        __syncthreads();

        float acc[2][8][4];
        #pragma unroll
        for (int mt = 0; mt < 2; mt++)
            #pragma unroll
            for (int nt = 0; nt < 8; nt++)
                #pragma unroll
                for (int r = 0; r < 4; r++) acc[mt][nt][r] = 0.f;
        mma_dd(Qs, Ps, acc, warpM, warpN, g, tg);

        #pragma unroll
        for (int mt = 0; mt < 2; mt++) {
            float r0m = NEG_INF_, r1m = NEG_INF_;
            #pragma unroll
            for (int nt = 0; nt < 8; nt++) {
                r0m = fmaxf(r0m, fmaxf(acc[mt][nt][0], acc[mt][nt][1]));
                r1m = fmaxf(r1m, fmaxf(acc[mt][nt][2], acc[mt][nt][3]));
            }
            r0m = fmaxf(r0m, __shfl_xor_sync(0xffffffffu, r0m, 1));
            r0m = fmaxf(r0m, __shfl_xor_sync(0xffffffffu, r0m, 2));
            r1m = fmaxf(r1m, __shfl_xor_sync(0xffffffffu, r1m, 1));
            r1m = fmaxf(r1m, __shfl_xor_sync(0xffffffffu, r1m, 2));
            if (tg == 0) {
                int n_a = warpM * 32 + mt * 16 + g;
                rowr[warpN * 64 + n_a]     = r0m;
                rowr[warpN * 64 + n_a + 8] = r1m;
            }
        }
        __syncthreads();

        if (c < 3) {
            #pragma unroll
            for (int i = 0; i < 4; i++) {
                int idx = t + i * 256;
                int r = idx >> 4, c4 = (idx & 15) * 4;
                *(float4*)(&Qs[r * AT_ST + c4]) = qreg[i];
            }
        }

        if (t < 64)
            srow[t] = fmaxf(fmaxf(rowr[t], rowr[64 + t]), fmaxf(rowr[128 + t], rowr[192 + t]));
        __syncthreads();

        #pragma unroll
        for (int mt = 0; mt < 2; mt++) {
            int n_a = warpM * 32 + mt * 16 + g;
            int n_b = n_a + 8;
            float oa = sdq[n_a] + srow[n_a], ob = sdq[n_b] + srow[n_b];
            float d0 = 0.f, d1 = 0.f;
            #pragma unroll
            for (int nt = 0; nt < 8; nt++) {
                int f0 = warpN * 64 + nt * 8 + tg * 2;
                float q0 = RATIO_ * (__expf(acc[mt][nt][0] - oa) + EPS_);
                float q1 = RATIO_ * (__expf(acc[mt][nt][1] - oa) + EPS_);
                float q2 = RATIO_ * (__expf(acc[mt][nt][2] - ob) + EPS_);
                float q3 = RATIO_ * (__expf(acc[mt][nt][3] - ob) + EPS_);
                acc[mt][nt][0] = q0; acc[mt][nt][1] = q1;
                acc[mt][nt][2] = q2; acc[mt][nt][3] = q3;
                float ks0 = sks[f0], ks1 = sks[f0 + 1];
                d0 += q0 * ks0 + q1 * ks1;
                d1 += q2 * ks0 + q3 * ks1;
            }
            d0 += __shfl_xor_sync(0xffffffffu, d0, 1);
            d0 += __shfl_xor_sync(0xffffffffu, d0, 2);
            d1 += __shfl_xor_sync(0xffffffffu, d1, 1);
            d1 += __shfl_xor_sync(0xffffffffu, d1, 2);
            if (tg == 0) {
                rowr[warpN * 64 + n_a] = d0;
                rowr[warpN * 64 + n_b] = d1;
            }
        }
        __syncthreads();
        if (t < 64)
            srow[t] = 1.0f / (rowr[t] + rowr[64 + t] + rowr[128 + t] + rowr[192 + t]);
        __syncthreads();

        #pragma unroll
        for (int mt = 0; mt < 2; mt++) {
            int n_a = warpM * 32 + mt * 16 + g;
            int n_b = n_a + 8;
            float ia = srow[n_a], ib = srow[n_b];
            #pragma unroll
            for (int nt = 0; nt < 8; nt++) {
                int f0 = warpN * 64 + nt * 8 + tg * 2;
                QPs[n_a * QP_ST + f0]     = acc[mt][nt][0] * ia;
                QPs[n_a * QP_ST + f0 + 1] = acc[mt][nt][1] * ia;
                QPs[n_b * QP_ST + f0]     = acc[mt][nt][2] * ib;
                QPs[n_b * QP_ST + f0 + 1] = acc[mt][nt][3] * ib;
            }
        }
        __syncthreads();

        float acc3[2][2][4];
        #pragma unroll
        for (int mt3 = 0; mt3 < 2; mt3++)
            #pragma unroll
            for (int nt3 = 0; nt3 < 2; nt3++)
                #pragma unroll
                for (int r = 0; r < 4; r++) acc3[mt3][nt3][r] = 0.f;
        #pragma unroll 4
        for (int kk = 0; kk < 32; kk++) {
            uint32_t af[2][4], bf[2][2];
            #pragma unroll
            for (int mt3 = 0; mt3 < 2; mt3++) {
                const float* a = QPs + (warpM * 32 + mt3 * 16 + g) * QP_ST + kk * 8 + tg;
                af[mt3][0] = f2tf(a[0]);
                af[mt3][1] = f2tf(a[8 * QP_ST]);
                af[mt3][2] = f2tf(a[4]);
                af[mt3][3] = f2tf(a[8 * QP_ST + 4]);
            }
            #pragma unroll
            for (int nt3 = 0; nt3 < 2; nt3++) {
                const float* bp_ = Cs + (kk * 8 + tg) * CX_ST + warpN * 16 + nt3 * 8 + g;
                bf[nt3][0] = f2tf(bp_[0]);
                bf[nt3][1] = f2tf(bp_[4 * CX_ST]);
            }
            #pragma unroll
            for (int mt3 = 0; mt3 < 2; mt3++)
                #pragma unroll
                for (int nt3 = 0; nt3 < 2; nt3++)
                    mma_tf32(acc3[mt3][nt3], af[mt3], bf[nt3]);
        }
        float* ob2 = g_attn + (size_t)(b * NPB + n0) * INNER + h * DH;
        #pragma unroll
        for (int mt3 = 0; mt3 < 2; mt3++) {
            int n = warpM * 32 + mt3 * 16 + g;
            #pragma unroll
            for (int nt3 = 0; nt3 < 2; nt3++) {
                int d = warpN * 16 + nt3 * 8 + tg * 2;
                *(float2*)(ob2 + (size_t)n * INNER + d)       = make_float2(acc3[mt3][nt3][0], acc3[mt3][nt3][1]);
                *(float2*)(ob2 + (size_t)(n + 8) * INNER + d) = make_float2(acc3[mt3][nt3][2], acc3[mt3][nt3][3]);
            }
        }
        __syncthreads();
    }
}

// ==================== TF32 MMA GEMM (4 warps, 64x64 warp tile, 3-stage) ====
#define BM 128
#define BN 128
#define BKT 32
#define AS_ST 36
#define BS_ST 136
#define GEMM_SMEM ((3*BM*AS_ST + 3*BKT*BS_ST) * 4)

template<int CVT, bool EPI>
__global__ __launch_bounds__(128, 2) void mma_gemm_kernel(
    const float* __restrict__ A, const float* __restrict__ B, float* __restrict__ C,
    int N, int K, const float* __restrict__ bt)
{
    extern __shared__ float smem[];
    float* As = smem;
    float* Bs = smem + 3 * BM * AS_ST;

    int tid = threadIdx.x;
    int lane = tid & 31, warp = tid >> 5;   // 4 warps: 2x2
    int wr = warp >> 1, wc = warp & 1;      // warp tile 64x64
    int g = lane >> 2, tg = lane & 3;

    float acc[4][8][4];
    #pragma unroll
    for (int mt = 0; mt < 4; mt++)
        #pragma unroll
        for (int nt = 0; nt < 8; nt++)
            #pragma unroll
            for (int r = 0; r < 4; r++) acc[mt][nt][r] = 0.f;

    const float* Abase = A + (size_t)blockIdx.y * BM * K;
    const float* Bbase = B + (size_t)blockIdx.x * BN;

    auto load_tile = [&](int kt, int buf) {
        const float* Ag = Abase + kt * BKT;
        #pragma unroll
        for (int i = 0; i < 8; i++) {
            int idx = tid + i * 128;
            int row = idx >> 3, c4 = (idx & 7) * 4;
            cp_async16(&As[buf * BM * AS_ST + row * AS_ST + c4], Ag + (size_t)row * K + c4);
        }
        const float* Bg = Bbase + (size_t)(kt * BKT) * N;
        #pragma unroll
        for (int i = 0; i < 8; i++) {
            int idx = tid + i * 128;
            int row = idx >> 5, c4 = (idx & 31) * 4;
            cp_async16(&Bs[buf * BKT * BS_ST + row * BS_ST + c4], Bg + (size_t)row * N + c4);
        }
        CP_COMMIT();
    };

    int KT = K / BKT;
    load_tile(0, 0);
    load_tile(1, 1);

    for (int kt = 0; kt < KT; kt++) {
        if (kt + 1 < KT) { asm volatile("cp.async.wait_group 1;\n"); }
        else             { asm volatile("cp.async.wait_group 0;\n"); }
        __syncthreads();
        if (kt + 2 < KT) load_tile(kt + 2, (kt + 2) % 3);

        const float* Ab = &As[(kt % 3) * BM * AS_ST];
        const float* Bb = &Bs[(kt % 3) * BKT * BS_ST];

        #pragma unroll
        for (int kk = 0; kk < 4; kk++) {
            uint32_t af[4][4], bf[8][2];
            #pragma unroll
            for (int mt = 0; mt < 4; mt++) {
                const float* base = Ab + (wr * 64 + mt * 16 + g) * AS_ST + kk * 8 + tg;
                float x0 = base[0];
                float x1 = base[8 * AS_ST];
                float x2 = base[4];
                float x3 = base[8 * AS_ST + 4];
                if (CVT) {
                    af[mt][0] = f2tf(x0); af[mt][1] = f2tf(x1);
                    af[mt][2] = f2tf(x2); af[mt][3] = f2tf(x3);
                } else {
                    af[mt][0] = __float_as_uint(x0); af[mt][1] = __float_as_uint(x1);
                    af[mt][2] = __float_as_uint(x2); af[mt][3] = __float_as_uint(x3);
                }
            }
            #pragma unroll
            for (int nt = 0; nt < 8; nt++) {
                const float* base = Bb + (kk * 8 + tg) * BS_ST + wc * 64 + nt * 8 + g;
                float y0 = base[0];
                float y1 = base[4 * BS_ST];
                if (CVT) {
                    bf[nt][0] = f2tf(y0); bf[nt][1] = f2tf(y1);
                } else {
                    bf[nt][0] = __float_as_uint(y0); bf[nt][1] = __float_as_uint(y1);
                }
            }
            #pragma unroll
            for (int mt = 0; mt < 4; mt++)
                #pragma unroll
                for (int nt = 0; nt < 8; nt++)
                    mma_tf32(acc[mt][nt], af[mt], bf[nt]);
        }
    }

    int rowBase = blockIdx.y * BM;
    int colBase = blockIdx.x * BN;
    #pragma unroll
    for (int mt = 0; mt < 4; mt++) {
        int r0 = rowBase + wr * 64 + mt * 16 + g;
        int r1 = r0 + 8;
        float b0 = 0.f, b1 = 0.f;
        if (EPI) {
            int p = r0 & (NPB - 1);
            int rel = (p >> 7) - (p & 127);
            rel = (rel < -7 ? -7 : (rel > 7 ? 7 : rel)) + 7;
            b0 = bt[rel];
            p = r1 & (NPB - 1);
            rel = (p >> 7) - (p & 127);
            rel = (rel < -7 ? -7 : (rel > 7 ? 7 : rel)) + 7;
            b1 = bt[rel];
        }
        #pragma unroll
        for (int nt = 0; nt < 8; nt++) {
            int cc = colBase + wc * 64 + nt * 8 + tg * 2;
            float2 v0, v1;
            if (EPI) {
                v0.x = acc[mt][nt][0] + g_bvec[cc]   + b0 * g_wpcol[cc];
                v0.y = acc[mt][nt][1] + g_bvec[cc+1] + b0 * g_wpcol[cc+1];
                v1.x = acc[mt][nt][2] + g_bvec[cc]   + b1 * g_wpcol[cc];
                v1.y = acc[mt][nt][3] + g_bvec[cc+1] + b1 * g_wpcol[cc+1];
            } else {
                v0 = make_float2(acc[mt][nt][0], acc[mt][nt][1]);
                v1 = make_float2(acc[mt][nt][2], acc[mt][nt][3]);
            }
            *(float2*)(C + (size_t)r0 * N + cc) = v0;
            *(float2*)(C + (size_t)r1 * N + cc) = v1;
        }
    }
}

// ---------------- launch ----------------
extern "C" void kernel_launch(void* const* d_in, const int* in_sizes, int n_in,
                              void* d_out, int out_size)
{
    const float* x    = (const float*)d_in[0];
    const float* Wq   = (const float*)d_in[1];
    const float* Wk   = (const float*)d_in[2];
    const float* Wv   = (const float*)d_in[3];
    const float* Wo   = (const float*)d_in[4];
    const float* bo   = (const float*)d_in[5];
    const float* proj = (const float*)d_in[6];
    const float* Wp   = (const float*)d_in[7];
    const float* bp   = (const float*)d_in[8];
    const float* bt   = (const float*)d_in[9];
    float* out = (float*)d_out;

    cudaFuncSetAttribute(mma_gemm_kernel<0, false>, cudaFuncAttributeMaxDynamicSharedMemorySize, GEMM_SMEM);
    cudaFuncSetAttribute(mma_gemm_kernel<1, true>,  cudaFuncAttributeMaxDynamicSharedMemorySize, GEMM_SMEM);
    cudaFuncSetAttribute(kctx_kernel2,  cudaFuncAttributeMaxDynamicSharedMemorySize, K2_SMEM);
    cudaFuncSetAttribute(qattn_kernel,  cudaFuncAttributeMaxDynamicSharedMemorySize, Q_SMEM);

    float *qkv_p, *wqkv_p, *attn_p, *wowp_p;
    cudaGetSymbolAddress((void**)&qkv_p,  g_qkv);
    cudaGetSymbolAddress((void**)&wqkv_p, g_Wqkv);
    cudaGetSymbolAddress((void**)&attn_p, g_attn);
    cudaGetSymbolAddress((void**)&wowp_p, g_WoWp);

    prep_kernel<<<INNER + 1, 256>>>(Wo, bo, Wp, bp);
    projprep_kernel<<<DH, NBF>>>(proj);
    pack_wqkv_kernel<<<C_, 512>>>(Wq, Wk, Wv);

    mma_gemm_kernel<0, false><<<dim3(QKVN / BN, NTOT / BM), 128, GEMM_SMEM>>>(
        x, wqkv_p, qkv_p, QKVN, C_, nullptr);

    kctx_kernel2<<<dim3(KSPLITS, BH), 256, K2_SMEM>>>();
    reduce2_kernel<<<(BH * NBF * DH) / 256, 256>>>();
    qattn_kernel<<<dim3(NPB / 256, BH), 256, Q_SMEM>>>();

    mma_gemm_kernel<1, true><<<dim3(C_ / BN, NTOT / BM), 128, GEMM_SMEM>>>(
        attn_p, wowp_p, out, C_, INNER, bt);
}

// round 15
// speedup vs baseline: 1.0749x; 1.0001x over previous
#include <cuda_runtime.h>
#include <math.h>
#include <stdint.h>

#define NPB    16384
#define NTOT   65536
#define C_     256
#define INNER  512
#define QKVN   1536
#define HEADS  8
#define DH     64
#define NBF    256
#define BH     32
#define EPS_   1e-4f
#define DN_    0.3535533905932738f
#define RATIO_ 0.0625f
#define KSPLITS 16
#define KCHUNKS 16
#define NEG_INF_ -3.0e38f

// ---------------- scratch ----------------
__device__ float g_qkv [(size_t)NTOT * QKVN];
__device__ float g_Wqkv[(size_t)C_ * QKVN];
__device__ float g_projT[DH * NBF];
__device__ float g_kmax[BH];
__device__ float g_pctx [(size_t)BH * KSPLITS * NBF * DH];
__device__ float g_pksum[(size_t)BH * KSPLITS * 2 * NBF];
__device__ float g_pvsum[(size_t)BH * KSPLITS * DH];
__device__ float g_ctx  [(size_t)BH * NBF * DH];
__device__ float g_ksum [(size_t)BH * NBF];
__device__ float g_attn[(size_t)NTOT * INNER];
__device__ float g_WoWp[(size_t)INNER * C_];
__device__ float g_bvec[C_];
__device__ float g_wpcol[C_];

static __device__ __forceinline__ void atomicMaxFloat(float* addr, float val) {
    int* ia = (int*)addr;
    int old = *ia;
    while (__int_as_float(old) < val) {
        int assumed = old;
        old = atomicCAS(ia, assumed, __float_as_int(val));
        if (old == assumed) break;
    }
}

// ---------------- prep ----------------
__global__ __launch_bounds__(256) void prep_kernel(
    const float* __restrict__ Wo, const float* __restrict__ bo,
    const float* __restrict__ Wp, const float* __restrict__ bp)
{
    int i = blockIdx.x, j = threadIdx.x;
    if (i < INNER) {
        __shared__ float wrow[C_];
        wrow[j] = Wo[i * C_ + j];
        __syncthreads();
        float s = 0.f;
        #pragma unroll 8
        for (int c = 0; c < C_; c++) s += wrow[c] * Wp[c * C_ + j];
        g_WoWp[i * C_ + j] = s;
    } else {
        float s = 0.f, w = 0.f;
        for (int c = 0; c < C_; c++) { float wp = Wp[c * C_ + j]; s += bo[c] * wp; w += wp; }
        g_bvec[j]  = s + bp[j];
        g_wpcol[j] = w;
        if (j < BH) g_kmax[j] = NEG_INF_;
    }
}

__global__ void projprep_kernel(const float* __restrict__ proj) {
    int d = blockIdx.x, f = threadIdx.x;
    g_projT[d * NBF + f] = proj[f * DH + d] * DN_;
}

__global__ __launch_bounds__(512) void pack_wqkv_kernel(
    const float* __restrict__ Wq, const float* __restrict__ Wk, const float* __restrict__ Wv)
{
    int i = blockIdx.x;
    int j = threadIdx.x;
    g_Wqkv[(size_t)i * QKVN + j]        = Wq[(size_t)i * INNER + j];
    g_Wqkv[(size_t)i * QKVN + 512 + j]  = Wk[(size_t)i * INNER + j];
    g_Wqkv[(size_t)i * QKVN + 1024 + j] = Wv[(size_t)i * INNER + j];
}

// ==================== common MMA helpers ====================
static __device__ __forceinline__ void cp_async16(float* s, const float* g) {
    unsigned saddr = (unsigned)__cvta_generic_to_shared(s);
    asm volatile("cp.async.cg.shared.global [%0], [%1], 16;\n" :: "r"(saddr), "l"(g));
}
#define CP_COMMIT() asm volatile("cp.async.commit_group;\n")
#define CP_WAIT0()  asm volatile("cp.async.wait_group 0;\n")

static __device__ __forceinline__ uint32_t f2tf(float x) {
    uint32_t r; asm("cvt.rna.tf32.f32 %0, %1;" : "=r"(r) : "f"(x)); return r;
}
static __device__ __forceinline__ void mma_tf32(float* c, const uint32_t* a, const uint32_t* b) {
    asm volatile("mma.sync.aligned.m16n8k8.row.col.f32.tf32.tf32.f32 "
        "{%0,%1,%2,%3},{%4,%5,%6,%7},{%8,%9},{%0,%1,%2,%3};"
        : "+f"(c[0]), "+f"(c[1]), "+f"(c[2]), "+f"(c[3])
        : "r"(a[0]), "r"(a[1]), "r"(a[2]), "r"(a[3]), "r"(b[0]), "r"(b[1]));
}

#define PJ_ST 264
#define AT_ST 68
#define VT_ST 72
#define KP_ST 76
#define QP_ST 260
#define CX_ST 72

static __device__ __forceinline__ void load_projT_s(float* ps, int t) {
    #pragma unroll
    for (int i = 0; i < 16; i++) {
        int idx = t + i * 256;
        int r = idx >> 6, c4 = (idx & 63) * 4;
        cp_async16(&ps[r * PJ_ST + c4], g_projT + r * 256 + c4);
    }
}
template<int ST>
static __device__ __forceinline__ void load_tile64(float* s, int b, int h, int n0, int off, int t) {
    #pragma unroll
    for (int i = 0; i < 4; i++) {
        int idx = t + i * 256;
        int r = idx >> 4, c4 = (idx & 15) * 4;
        cp_async16(&s[r * ST + c4],
            g_qkv + (size_t)(b * NPB + n0 + r) * QKVN + off + h * DH + c4);
    }
}

// dd[n][f] = tile @ projT : M=64 (2 warps x32), N=256 (4 warps x64), K=64
static __device__ __forceinline__ void mma_dd(
    const float* __restrict__ As, const float* __restrict__ Ps,
    float acc[2][8][4], int warpM, int warpN, int g, int tg)
{
    #pragma unroll
    for (int kk = 0; kk < 8; kk++) {
        uint32_t af[2][4], bf[8][2];
        #pragma unroll
        for (int mt = 0; mt < 2; mt++) {
            const float* a = As + (warpM * 32 + mt * 16 + g) * AT_ST + kk * 8 + tg;
            af[mt][0] = f2tf(a[0]);
            af[mt][1] = f2tf(a[8 * AT_ST]);
            af[mt][2] = f2tf(a[4]);
            af[mt][3] = f2tf(a[8 * AT_ST + 4]);
        }
        #pragma unroll
        for (int nt = 0; nt < 8; nt++) {
            const float* bp_ = Ps + (kk * 8 + tg) * PJ_ST + warpN * 64 + nt * 8 + g;
            bf[nt][0] = f2tf(bp_[0]);
            bf[nt][1] = f2tf(bp_[4 * PJ_ST]);
        }
        #pragma unroll
        for (int mt = 0; mt < 2; mt++)
            #pragma unroll
            for (int nt = 0; nt < 8; nt++)
                mma_tf32(acc[mt][nt], af[mt], bf[nt]);
    }
}

// ==================== K2: key features -> partial (unscaled) ctx/ksum + max + vsum ====
#define K2_SMEM ((64*PJ_ST + 2*64*AT_ST + 2*64*VT_ST + 256*KP_ST + 64 + 256) * 4)
__global__ __launch_bounds__(256, 1) void kctx_kernel2()
{
    extern __shared__ float sm[];
    float* Ps    = sm;
    float* Ks    = Ps + 64 * PJ_ST;
    float* Vs    = Ks + 2 * 64 * AT_ST;
    float* KPs   = Vs + 2 * 64 * VT_ST;
    float* sdiag = KPs + 256 * KP_ST;
    float* red   = sdiag + 64;
    int t = threadIdx.x;
    int bh = blockIdx.y, b = bh >> 3, h = bh & 7;
    int sp = blockIdx.x;
    int warp = t >> 5, lane = t & 31, g = lane >> 2, tg = lane & 3;
    int warpM = warp >> 2, warpN = warp & 3;
    int warpM2 = warp >> 1, warpN2 = warp & 1;
    int prow = t >> 2, pq = t & 3;

    load_projT_s(Ps, t);
    float acc2[4][4][4];
    #pragma unroll
    for (int a = 0; a < 4; a++)
        #pragma unroll
        for (int bq = 0; bq < 4; bq++)
            #pragma unroll
            for (int r = 0; r < 4; r++) acc2[a][bq][r] = 0.f;
    float ksacc[8][2];
    #pragma unroll
    for (int nt = 0; nt < 8; nt++) { ksacc[nt][0] = 0.f; ksacc[nt][1] = 0.f; }
    float tmax = NEG_INF_;
    float vsum_acc = 0.f;

    load_tile64<AT_ST>(Ks, b, h, sp * (64 * KCHUNKS), 512, t);
    load_tile64<VT_ST>(Vs, b, h, sp * (64 * KCHUNKS), 1024, t);
    CP_COMMIT();

    for (int c = 0; c < KCHUNKS; c++) {
        CP_WAIT0();
        __syncthreads();
        float* Kb = Ks + (c & 1) * 64 * AT_ST;
        float* Vb = Vs + (c & 1) * 64 * VT_ST;
        if (c + 1 < KCHUNKS) {
            int n1 = sp * (64 * KCHUNKS) + (c + 1) * 64;
            load_tile64<AT_ST>(Ks + ((c + 1) & 1) * 64 * AT_ST, b, h, n1, 512, t);
            load_tile64<VT_ST>(Vs + ((c + 1) & 1) * 64 * VT_ST, b, h, n1, 1024, t);
            CP_COMMIT();
        }
        {
            const float4* kr = (const float4*)(Kb + prow * AT_ST + pq * 16);
            float s = 0.f;
            #pragma unroll
            for (int j = 0; j < 4; j++) {
                float4 v = kr[j];
                s += v.x * v.x + v.y * v.y + v.z * v.z + v.w * v.w;
            }
            s += __shfl_xor_sync(0xffffffffu, s, 1);
            s += __shfl_xor_sync(0xffffffffu, s, 2);
            if (pq == 0) sdiag[prow] = 0.5f * s * (DN_ * DN_);
            float vsp = 0.f;
            #pragma unroll
            for (int i = 0; i < 16; i++) {
                int r = pq * 16 + ((i + pq) & 15);
                vsp += Vb[r * VT_ST + prow];
            }
            vsum_acc += vsp;
        }

        float acc[2][8][4];
        #pragma unroll
        for (int mt = 0; mt < 2; mt++)
            #pragma unroll
            for (int nt = 0; nt < 8; nt++)
                #pragma unroll
                for (int r = 0; r < 4; r++) acc[mt][nt][r] = 0.f;
        mma_dd(Kb, Ps, acc, warpM, warpN, g, tg);
        __syncthreads();

        float s0a[8], s1a[8];
        #pragma unroll
        for (int nt = 0; nt < 8; nt++) { s0a[nt] = 0.f; s1a[nt] = 0.f; }
        #pragma unroll
        for (int mt = 0; mt < 2; mt++) {
            int n_a = warpM * 32 + mt * 16 + g;
            int n_b = n_a + 8;
            float da = sdiag[n_a], db = sdiag[n_b];
            #pragma unroll
            for (int nt = 0; nt < 8; nt++) {
                int f0 = warpN * 64 + nt * 8 + tg * 2;
                float d0 = acc[mt][nt][0], d1 = acc[mt][nt][1];
                float d2 = acc[mt][nt][2], d3 = acc[mt][nt][3];
                tmax = fmaxf(tmax, fmaxf(fmaxf(d0, d1), fmaxf(d2, d3)));
                float k0 = __expf(d0 - da);
                float k1 = __expf(d1 - da);
                float k2 = __expf(d2 - db);
                float k3 = __expf(d3 - db);
                KPs[f0 * KP_ST + n_a]       = k0;
                KPs[(f0 + 1) * KP_ST + n_a] = k1;
                KPs[f0 * KP_ST + n_b]       = k2;
                KPs[(f0 + 1) * KP_ST + n_b] = k3;
                s0a[nt] += k0 + k2;
                s1a[nt] += k1 + k3;
            }
        }
        #pragma unroll
        for (int nt = 0; nt < 8; nt++) {
            float s0 = s0a[nt], s1 = s1a[nt];
            #pragma unroll
            for (int o = 4; o <= 16; o <<= 1) {
                s0 += __shfl_xor_sync(0xffffffffu, s0, o);
                s1 += __shfl_xor_sync(0xffffffffu, s1, o);
            }
            ksacc[nt][0] += s0; ksacc[nt][1] += s1;
        }
        __syncthreads();

        #pragma unroll
        for (int kk = 0; kk < 8; kk++) {
            uint32_t af[4][4], bf[4][2];
            #pragma unroll
            for (int mt2 = 0; mt2 < 4; mt2++) {
                const float* a = KPs + (warpM2 * 64 + mt2 * 16 + g) * KP_ST + kk * 8 + tg;
                af[mt2][0] = f2tf(a[0]);
                af[mt2][1] = f2tf(a[8 * KP_ST]);
                af[mt2][2] = f2tf(a[4]);
                af[mt2][3] = f2tf(a[8 * KP_ST + 4]);
            }
            #pragma unroll
            for (int nt2 = 0; nt2 < 4; nt2++) {
                const float* bp_ = Vb + (kk * 8 + tg) * VT_ST + warpN2 * 32 + nt2 * 8 + g;
                bf[nt2][0] = f2tf(bp_[0]);
                bf[nt2][1] = f2tf(bp_[4 * VT_ST]);
            }
            #pragma unroll
            for (int mt2 = 0; mt2 < 4; mt2++)
                #pragma unroll
                for (int nt2 = 0; nt2 < 4; nt2++)
                    mma_tf32(acc2[mt2][nt2], af[mt2], bf[nt2]);
        }
    }

    red[t] = tmax; __syncthreads();
    for (int s = 128; s > 0; s >>= 1) {
        if (t < s) red[t] = fmaxf(red[t], red[t + s]);
        __syncthreads();
    }
    if (t == 0) atomicMaxFloat(&g_kmax[bh], red[0]);

    float* outp = g_pctx + ((size_t)bh * KSPLITS + sp) * NBF * DH;
    #pragma unroll
    for (int mt2 = 0; mt2 < 4; mt2++) {
        int f = warpM2 * 64 + mt2 * 16 + g;
        #pragma unroll
        for (int nt2 = 0; nt2 < 4; nt2++) {
            int d = warpN2 * 32 + nt2 * 8 + tg * 2;
            *(float2*)(outp + (size_t)f * DH + d)       = make_float2(acc2[mt2][nt2][0], acc2[mt2][nt2][1]);
            *(float2*)(outp + (size_t)(f + 8) * DH + d) = make_float2(acc2[mt2][nt2][2], acc2[mt2][nt2][3]);
        }
    }
    if (g == 0) {
        float* kout = g_pksum + (((size_t)bh * KSPLITS + sp) * 2 + warpM) * NBF;
        #pragma unroll
        for (int nt = 0; nt < 8; nt++) {
            int f0 = warpN * 64 + nt * 8 + tg * 2;
            kout[f0]     = ksacc[nt][0];
            kout[f0 + 1] = ksacc[nt][1];
        }
    }
    vsum_acc += __shfl_xor_sync(0xffffffffu, vsum_acc, 1);
    vsum_acc += __shfl_xor_sync(0xffffffffu, vsum_acc, 2);
    if (pq == 0) g_pvsum[((size_t)bh * KSPLITS + sp) * DH + prow] = vsum_acc;
}

// ---------------- deterministic reduction with rescale + EPS terms ----------------
__global__ __launch_bounds__(256) void reduce2_kernel()
{
    int idx = blockIdx.x * 256 + threadIdx.x;
    int bh = idx >> 14;
    int rem = idx & 16383;
    int d = rem & 63;
    float m = g_kmax[bh];
    float sc = RATIO_ * __expf(-m);
    float s = 0.f;
    const float* base = g_pctx + (size_t)bh * KSPLITS * NBF * DH + rem;
    #pragma unroll
    for (int sp = 0; sp < KSPLITS; sp++) s += base[(size_t)sp * NBF * DH];
    float vs = 0.f;
    const float* vb = g_pvsum + (size_t)bh * KSPLITS * DH + d;
    #pragma unroll
    for (int sp = 0; sp < KSPLITS; sp++) vs += vb[sp * DH];
    g_ctx[idx] = sc * s + (RATIO_ * EPS_) * vs;
    if (idx < BH * NBF) {
        int bh2 = idx >> 8, f = idx & 255;
        float m2 = g_kmax[bh2];
        float s2 = 0.f;
        const float* kb = g_pksum + (size_t)bh2 * KSPLITS * 2 * NBF + f;
        #pragma unroll
        for (int j = 0; j < KSPLITS * 2; j++) s2 += kb[j * NBF];
        g_ksum[idx] = RATIO_ * __expf(-m2) * s2 + (RATIO_ * EPS_) * (float)NPB;
    }
}

// ==================== Q: fused query features + attention (512 rows / block) ====
#define Q_SMEM ((64*PJ_ST + 256*CX_ST + 64*AT_ST + 64*QP_ST + 256 + 64 + 256 + 64) * 4)
__global__ __launch_bounds__(256, 1) void qattn_kernel()
{
    extern __shared__ float sm[];
    float* Ps   = sm;
    float* Cs   = Ps + 64 * PJ_ST;
    float* Qs   = Cs + 256 * CX_ST;
    float* QPs  = Qs + 64 * AT_ST;
    float* sks  = QPs + 64 * QP_ST;
    float* sdq  = sks + 256;
    float* rowr = sdq + 64;
    float* srow = rowr + 256;
    int t = threadIdx.x;
    int bh = blockIdx.y, b = bh >> 3, h = bh & 7;
    int warp = t >> 5, lane = t & 31, g = lane >> 2, tg = lane & 3;
    int warpM = warp >> 2, warpN = warp & 3;

    load_projT_s(Ps, t);
    #pragma unroll
    for (int i = 0; i < 16; i++) {
        int idx = t + i * 256;
        int r = idx >> 4, c4 = (idx & 15) * 4;
        cp_async16(&Cs[r * CX_ST + c4], g_ctx + (size_t)bh * NBF * DH + r * DH + c4);
    }
    sks[t] = g_ksum[bh * NBF + t];
    load_tile64<AT_ST>(Qs, b, h, blockIdx.x * 512, 0, t);
    CP_COMMIT();

    for (int c = 0; c < 8; c++) {
        int n0 = blockIdx.x * 512 + c * 64;
        if (c == 0) { CP_WAIT0(); __syncthreads(); }

        float4 qreg[4];
        if (c < 7) {
            int n1 = blockIdx.x * 512 + (c + 1) * 64;
            #pragma unroll
            for (int i = 0; i < 4; i++) {
                int idx = t + i * 256;
                int r = idx >> 4, c4 = (idx & 15) * 4;
                qreg[i] = *(const float4*)(g_qkv + (size_t)(b * NPB + n1 + r) * QKVN + h * DH + c4);
            }
        }

        if (t < 64) {
            float s = 0.f;
            #pragma unroll
            for (int d = 0; d < 64; d++) { float qv = Qs[t * AT_ST + d]; s += qv * qv; }
            sdq[t] = 0.5f * s * (DN_ * DN_);
        }
        __syncthreads();

        float acc[2][8][4];
        #pragma unroll
        for (int mt = 0; mt < 2; mt++)
            #pragma unroll
            for (int nt = 0; nt < 8; nt++)
                #pragma unroll
                for (int r = 0; r < 4; r++) acc[mt][nt][r] = 0.f;
        mma_dd(Qs, Ps, acc, warpM, warpN, g, tg);

        #pragma unroll
        for (int mt = 0; mt < 2; mt++) {
            float r0m = NEG_INF_, r1m = NEG_INF_;
            #pragma unroll
            for (int nt = 0; nt < 8; nt++) {
                r0m = fmaxf(r0m, fmaxf(acc[mt][nt][0], acc[mt][nt][1]));
                r1m = fmaxf(r1m, fmaxf(acc[mt][nt][2], acc[mt][nt][3]));
            }
            r0m = fmaxf(r0m, __shfl_xor_sync(0xffffffffu, r0m, 1));
            r0m = fmaxf(r0m, __shfl_xor_sync(0xffffffffu, r0m, 2));
            r1m = fmaxf(r1m, __shfl_xor_sync(0xffffffffu, r1m, 1));
            r1m = fmaxf(r1m, __shfl_xor_sync(0xffffffffu, r1m, 2));
            if (tg == 0) {
                int n_a = warpM * 32 + mt * 16 + g;
                rowr[warpN * 64 + n_a]     = r0m;
                rowr[warpN * 64 + n_a + 8] = r1m;
            }
        }
        __syncthreads();

        if (c < 7) {
            #pragma unroll
            for (int i = 0; i < 4; i++) {
                int idx = t + i * 256;
                int r = idx >> 4, c4 = (idx & 15) * 4;
                *(float4*)(&Qs[r * AT_ST + c4]) = qreg[i];
            }
        }

        if (t < 64)
            srow[t] = fmaxf(fmaxf(rowr[t], rowr[64 + t]), fmaxf(rowr[128 + t], rowr[192 + t]));
        __syncthreads();

        #pragma unroll
        for (int mt = 0; mt < 2; mt++) {
            int n_a = warpM * 32 + mt * 16 + g;
            int n_b = n_a + 8;
            float oa = sdq[n_a] + srow[n_a], ob = sdq[n_b] + srow[n_b];
            float d0 = 0.f, d1 = 0.f;
            #pragma unroll
            for (int nt = 0; nt < 8; nt++) {
                int f0 = warpN * 64 + nt * 8 + tg * 2;
                float q0 = RATIO_ * (__expf(acc[mt][nt][0] - oa) + EPS_);
                float q1 = RATIO_ * (__expf(acc[mt][nt][1] - oa) + EPS_);
                float q2 = RATIO_ * (__expf(acc[mt][nt][2] - ob) + EPS_);
                float q3 = RATIO_ * (__expf(acc[mt][nt][3] - ob) + EPS_);
                acc[mt][nt][0] = q0; acc[mt][nt][1] = q1;
                acc[mt][nt][2] = q2; acc[mt][nt][3] = q3;
                float ks0 = sks[f0], ks1 = sks[f0 + 1];
                d0 += q0 * ks0 + q1 * ks1;
                d1 += q2 * ks0 + q3 * ks1;
            }
            d0 += __shfl_xor_sync(0xffffffffu, d0, 1);
            d0 += __shfl_xor_sync(0xffffffffu, d0, 2);
            d1 += __shfl_xor_sync(0xffffffffu, d1, 1);
            d1 += __shfl_xor_sync(0xffffffffu, d1, 2);
            if (tg == 0) {
                rowr[warpN * 64 + n_a] = d0;
                rowr[warpN * 64 + n_b] = d1;
            }
        }
        __syncthreads();
        if (t < 64)
            srow[t] = 1.0f / (rowr[t] + rowr[64 + t] + rowr[128 + t] + rowr[192 + t]);
        __syncthreads();

        #pragma unroll
        for (int mt = 0; mt < 2; mt++) {
            int n_a = warpM * 32 + mt * 16 + g;
            int n_b = n_a + 8;
            float ia = srow[n_a], ib = srow[n_b];
            #pragma unroll
            for (int nt = 0; nt < 8; nt++) {
                int f0 = warpN * 64 + nt * 8 + tg * 2;
                QPs[n_a * QP_ST + f0]     = acc[mt][nt][0] * ia;
                QPs[n_a * QP_ST + f0 + 1] = acc[mt][nt][1] * ia;
                QPs[n_b * QP_ST + f0]     = acc[mt][nt][2] * ib;
                QPs[n_b * QP_ST + f0 + 1] = acc[mt][nt][3] * ib;
            }
        }
        __syncthreads();

        float acc3[2][2][4];
        #pragma unroll
        for (int mt3 = 0; mt3 < 2; mt3++)
            #pragma unroll
            for (int nt3 = 0; nt3 < 2; nt3++)
                #pragma unroll
                for (int r = 0; r < 4; r++) acc3[mt3][nt3][r] = 0.f;
        #pragma unroll 4
        for (int kk = 0; kk < 32; kk++) {
            uint32_t af[2][4], bf[2][2];
            #pragma unroll
            for (int mt3 = 0; mt3 < 2; mt3++) {
                const float* a = QPs + (warpM * 32 + mt3 * 16 + g) * QP_ST + kk * 8 + tg;
                af[mt3][0] = f2tf(a[0]);
                af[mt3][1] = f2tf(a[8 * QP_ST]);
                af[mt3][2] = f2tf(a[4]);
                af[mt3][3] = f2tf(a[8 * QP_ST + 4]);
            }
            #pragma unroll
            for (int nt3 = 0; nt3 < 2; nt3++) {
                const float* bp_ = Cs + (kk * 8 + tg) * CX_ST + warpN * 16 + nt3 * 8 + g;
                bf[nt3][0] = f2tf(bp_[0]);
                bf[nt3][1] = f2tf(bp_[4 * CX_ST]);
            }
            #pragma unroll
            for (int mt3 = 0; mt3 < 2; mt3++)
                #pragma unroll
                for (int nt3 = 0; nt3 < 2; nt3++)
                    mma_tf32(acc3[mt3][nt3], af[mt3], bf[nt3]);
        }
        float* ob2 = g_attn + (size_t)(b * NPB + n0) * INNER + h * DH;
        #pragma unroll
        for (int mt3 = 0; mt3 < 2; mt3++) {
            int n = warpM * 32 + mt3 * 16 + g;
            #pragma unroll
            for (int nt3 = 0; nt3 < 2; nt3++) {
                int d = warpN * 16 + nt3 * 8 + tg * 2;
                *(float2*)(ob2 + (size_t)n * INNER + d)       = make_float2(acc3[mt3][nt3][0], acc3[mt3][nt3][1]);
                *(float2*)(ob2 + (size_t)(n + 8) * INNER + d) = make_float2(acc3[mt3][nt3][2], acc3[mt3][nt3][3]);
            }
        }
        __syncthreads();
    }
}

// ==================== TF32 MMA GEMM (4 warps, 64x64 warp tile, 3-stage) ====
#define BM 128
#define BN 128
#define BKT 32
#define AS_ST 36
#define BS_ST 136
#define GEMM_SMEM ((3*BM*AS_ST + 3*BKT*BS_ST) * 4)

template<int CVT, bool EPI>
__global__ __launch_bounds__(128, 2) void mma_gemm_kernel(
    const float* __restrict__ A, const float* __restrict__ B, float* __restrict__ C,
    int N, int K, const float* __restrict__ bt)
{
    extern __shared__ float smem[];
    float* As = smem;
    float* Bs = smem + 3 * BM * AS_ST;

    int tid = threadIdx.x;
    int lane = tid & 31, warp = tid >> 5;
    int wr = warp >> 1, wc = warp & 1;
    int g = lane >> 2, tg = lane & 3;

    float acc[4][8][4];
    #pragma unroll
    for (int mt = 0; mt < 4; mt++)
        #pragma unroll
        for (int nt = 0; nt < 8; nt++)
            #pragma unroll
            for (int r = 0; r < 4; r++) acc[mt][nt][r] = 0.f;

    const float* Abase = A + (size_t)blockIdx.y * BM * K;
    const float* Bbase = B + (size_t)blockIdx.x * BN;

    auto load_tile = [&](int kt, int buf) {
        const float* Ag = Abase + kt * BKT;
        #pragma unroll
        for (int i = 0; i < 8; i++) {
            int idx = tid + i * 128;
            int row = idx >> 3, c4 = (idx & 7) * 4;
            cp_async16(&As[buf * BM * AS_ST + row * AS_ST + c4], Ag + (size_t)row * K + c4);
        }
        const float* Bg = Bbase + (size_t)(kt * BKT) * N;
        #pragma unroll
        for (int i = 0; i < 8; i++) {
            int idx = tid + i * 128;
            int row = idx >> 5, c4 = (idx & 31) * 4;
            cp_async16(&Bs[buf * BKT * BS_ST + row * BS_ST + c4], Bg + (size_t)row * N + c4);
        }
        CP_COMMIT();
    };

    int KT = K / BKT;
    load_tile(0, 0);
    load_tile(1, 1);

    for (int kt = 0; kt < KT; kt++) {
        if (kt + 1 < KT) { asm volatile("cp.async.wait_group 1;\n"); }
        else             { asm volatile("cp.async.wait_group 0;\n"); }
        __syncthreads();
        if (kt + 2 < KT) load_tile(kt + 2, (kt + 2) % 3);

        const float* Ab = &As[(kt % 3) * BM * AS_ST];
        const float* Bb = &Bs[(kt % 3) * BKT * BS_ST];

        #pragma unroll
        for (int kk = 0; kk < 4; kk++) {
            uint32_t af[4][4], bf[8][2];
            #pragma unroll
            for (int mt = 0; mt < 4; mt++) {
                const float* base = Ab + (wr * 64 + mt * 16 + g) * AS_ST + kk * 8 + tg;
                float x0 = base[0];
                float x1 = base[8 * AS_ST];
                float x2 = base[4];
                float x3 = base[8 * AS_ST + 4];
                if (CVT) {
                    af[mt][0] = f2tf(x0); af[mt][1] = f2tf(x1);
                    af[mt][2] = f2tf(x2); af[mt][3] = f2tf(x3);
                } else {
                    af[mt][0] = __float_as_uint(x0); af[mt][1] = __float_as_uint(x1);
                    af[mt][2] = __float_as_uint(x2); af[mt][3] = __float_as_uint(x3);
                }
            }
            #pragma unroll
            for (int nt = 0; nt < 8; nt++) {
                const float* base = Bb + (kk * 8 + tg) * BS_ST + wc * 64 + nt * 8 + g;
                float y0 = base[0];
                float y1 = base[4 * BS_ST];
                if (CVT) {
                    bf[nt][0] = f2tf(y0); bf[nt][1] = f2tf(y1);
                } else {
                    bf[nt][0] = __float_as_uint(y0); bf[nt][1] = __float_as_uint(y1);
                }
            }
            #pragma unroll
            for (int mt = 0; mt < 4; mt++)
                #pragma unroll
                for (int nt = 0; nt < 8; nt++)
                    mma_tf32(acc[mt][nt], af[mt], bf[nt]);
        }
    }

    int rowBase = blockIdx.y * BM;
    int colBase = blockIdx.x * BN;
    #pragma unroll
    for (int mt = 0; mt < 4; mt++) {
        int r0 = rowBase + wr * 64 + mt * 16 + g;
        int r1 = r0 + 8;
        float b0 = 0.f, b1 = 0.f;
        if (EPI) {
            int p = r0 & (NPB - 1);
            int rel = (p >> 7) - (p & 127);
            rel = (rel < -7 ? -7 : (rel > 7 ? 7 : rel)) + 7;
            b0 = bt[rel];
            p = r1 & (NPB - 1);
            rel = (p >> 7) - (p & 127);
            rel = (rel < -7 ? -7 : (rel > 7 ? 7 : rel)) + 7;
            b1 = bt[rel];
        }
        #pragma unroll
        for (int nt = 0; nt < 8; nt++) {
            int cc = colBase + wc * 64 + nt * 8 + tg * 2;
            float2 v0, v1;
            if (EPI) {
                v0.x = acc[mt][nt][0] + g_bvec[cc]   + b0 * g_wpcol[cc];
                v0.y = acc[mt][nt][1] + g_bvec[cc+1] + b0 * g_wpcol[cc+1];
                v1.x = acc[mt][nt][2] + g_bvec[cc]   + b1 * g_wpcol[cc];
                v1.y = acc[mt][nt][3] + g_bvec[cc+1] + b1 * g_wpcol[cc+1];
            } else {
                v0 = make_float2(acc[mt][nt][0], acc[mt][nt][1]);
                v1 = make_float2(acc[mt][nt][2], acc[mt][nt][3]);
            }
            *(float2*)(C + (size_t)r0 * N + cc) = v0;
            *(float2*)(C + (size_t)r1 * N + cc) = v1;
        }
    }
}

// ---------------- launch ----------------
extern "C" void kernel_launch(void* const* d_in, const int* in_sizes, int n_in,
                              void* d_out, int out_size)
{
    const float* x    = (const float*)d_in[0];
    const float* Wq   = (const float*)d_in[1];
    const float* Wk   = (const float*)d_in[2];
    const float* Wv   = (const float*)d_in[3];
    const float* Wo   = (const float*)d_in[4];
    const float* bo   = (const float*)d_in[5];
    const float* proj = (const float*)d_in[6];
    const float* Wp   = (const float*)d_in[7];
    const float* bp   = (const float*)d_in[8];
    const float* bt   = (const float*)d_in[9];
    float* out = (float*)d_out;

    cudaFuncSetAttribute(mma_gemm_kernel<0, false>, cudaFuncAttributeMaxDynamicSharedMemorySize, GEMM_SMEM);
    cudaFuncSetAttribute(mma_gemm_kernel<1, true>,  cudaFuncAttributeMaxDynamicSharedMemorySize, GEMM_SMEM);
    cudaFuncSetAttribute(kctx_kernel2,  cudaFuncAttributeMaxDynamicSharedMemorySize, K2_SMEM);
    cudaFuncSetAttribute(qattn_kernel,  cudaFuncAttributeMaxDynamicSharedMemorySize, Q_SMEM);

    float *qkv_p, *wqkv_p, *attn_p, *wowp_p;
    cudaGetSymbolAddress((void**)&qkv_p,  g_qkv);
    cudaGetSymbolAddress((void**)&wqkv_p, g_Wqkv);
    cudaGetSymbolAddress((void**)&attn_p, g_attn);
    cudaGetSymbolAddress((void**)&wowp_p, g_WoWp);

    prep_kernel<<<INNER + 1, 256>>>(Wo, bo, Wp, bp);
    projprep_kernel<<<DH, NBF>>>(proj);
    pack_wqkv_kernel<<<C_, 512>>>(Wq, Wk, Wv);

    mma_gemm_kernel<0, false><<<dim3(QKVN / BN, NTOT / BM), 128, GEMM_SMEM>>>(
        x, wqkv_p, qkv_p, QKVN, C_, nullptr);

    kctx_kernel2<<<dim3(KSPLITS, BH), 256, K2_SMEM>>>();
    reduce2_kernel<<<(BH * NBF * DH) / 256, 256>>>();
    qattn_kernel<<<dim3(NPB / 512, BH), 256, Q_SMEM>>>();

    mma_gemm_kernel<1, true><<<dim3(C_ / BN, NTOT / BM), 128, GEMM_SMEM>>>(
        attn_p, wowp_p, out, C_, INNER, bt);
}